// round 1
// baseline (speedup 1.0000x reference)
#include <cuda_runtime.h>
#include <cstdint>
#include <math.h>

#define EMBED    1024
#define HEADS    16
#define HEAD_DIM 64
#define BATCH    2
#define SEQ      2048
#define TOKENS   (BATCH * SEQ)

// ---------------------------------------------------------------------------
// Scratch (device globals: the sanctioned alloc-free workaround)
// ---------------------------------------------------------------------------
__device__ float g_q [TOKENS * EMBED];
__device__ float g_k [TOKENS * EMBED];
__device__ float g_v [TOKENS * EMBED];
__device__ float g_ao[TOKENS * EMBED];

__device__ __forceinline__ float fast_exp2(float x) {
    float y;
    asm("ex2.approx.f32 %0, %1;" : "=f"(y) : "f"(x));
    return y;
}

// ---------------------------------------------------------------------------
// SGEMM: C[M,N] = A[M,K] @ B[N,K]^T + bias[N]
// 128x128 block tile, BK=8, 256 threads, 8x8 per-thread register tile.
// ---------------------------------------------------------------------------
__global__ __launch_bounds__(256, 2)
void gemm_bias_kernel(const float* __restrict__ A,
                      const float* __restrict__ Bw,
                      const float* __restrict__ bias,
                      float* __restrict__ C,
                      int M, int N, int K)
{
    __shared__ float As[8][132];   // [k][m], +4 pad -> conflict-free stores
    __shared__ float Bs[8][132];   // [k][n]

    const int tid = threadIdx.x;
    const int tx  = tid & 15;
    const int ty  = tid >> 4;
    const int row0 = blockIdx.y * 128;
    const int col0 = blockIdx.x * 128;

    const int lr = tid >> 1;        // 0..127
    const int lc = (tid & 1) * 4;   // 0 or 4

    const float* Ap = A  + (size_t)(row0 + lr) * K + lc;
    const float* Bp = Bw + (size_t)(col0 + lr) * K + lc;

    float acc[8][8];
#pragma unroll
    for (int i = 0; i < 8; i++)
#pragma unroll
        for (int j = 0; j < 8; j++) acc[i][j] = 0.0f;

    float4 a4 = *(const float4*)(Ap);
    float4 b4 = *(const float4*)(Bp);

    for (int k0 = 0; k0 < K; k0 += 8) {
        As[lc + 0][lr] = a4.x; As[lc + 1][lr] = a4.y;
        As[lc + 2][lr] = a4.z; As[lc + 3][lr] = a4.w;
        Bs[lc + 0][lr] = b4.x; Bs[lc + 1][lr] = b4.y;
        Bs[lc + 2][lr] = b4.z; Bs[lc + 3][lr] = b4.w;
        __syncthreads();

        if (k0 + 8 < K) {
            a4 = *(const float4*)(Ap + k0 + 8);
            b4 = *(const float4*)(Bp + k0 + 8);
        }

#pragma unroll
        for (int kk = 0; kk < 8; kk++) {
            float4 a0 = *(const float4*)&As[kk][ty * 8];
            float4 a1 = *(const float4*)&As[kk][ty * 8 + 4];
            float4 b0 = *(const float4*)&Bs[kk][tx * 8];
            float4 b1 = *(const float4*)&Bs[kk][tx * 8 + 4];
            float ar[8] = {a0.x, a0.y, a0.z, a0.w, a1.x, a1.y, a1.z, a1.w};
            float br[8] = {b0.x, b0.y, b0.z, b0.w, b1.x, b1.y, b1.z, b1.w};
#pragma unroll
            for (int i = 0; i < 8; i++)
#pragma unroll
                for (int j = 0; j < 8; j++)
                    acc[i][j] += ar[i] * br[j];
        }
        __syncthreads();
    }

    float4 bb0 = *(const float4*)(bias + col0 + tx * 8);
    float4 bb1 = *(const float4*)(bias + col0 + tx * 8 + 4);
#pragma unroll
    for (int i = 0; i < 8; i++) {
        const int r = row0 + ty * 8 + i;
        float4 c0 = make_float4(acc[i][0] + bb0.x, acc[i][1] + bb0.y,
                                acc[i][2] + bb0.z, acc[i][3] + bb0.w);
        float4 c1 = make_float4(acc[i][4] + bb1.x, acc[i][5] + bb1.y,
                                acc[i][6] + bb1.z, acc[i][7] + bb1.w);
        float* Cp = C + (size_t)r * N + col0 + tx * 8;
        *(float4*)(Cp)     = c0;
        *(float4*)(Cp + 4) = c1;
    }
}

// ---------------------------------------------------------------------------
// Flash attention, fp32. One CTA per (b, h, 128-query tile).
// Q/K held d-major (transposed) with XOR swizzle; P transposed with XOR
// swizzle. Both matmul phases use 8x8 SGEMM-style register tiles.
// ---------------------------------------------------------------------------

// smem layout (floats): Qs[64*128] | Ks[64*128] | Vs[128*64] | Ps[128*128] | msk[128 ints]
#define ATT_SMEM ((3 * 64 * 128 + 128 * 128) * 4 + 128 * 4)

__device__ __forceinline__ int qswz(int d, int q) {          // [d][q] swizzled
    return d * 128 + ((((q >> 2) ^ (d & 31)) << 2) | (q & 3));
}
__device__ __forceinline__ int pswz(int k, int q) {          // [k][q] swizzled
    return k * 128 + ((((q >> 2) ^ ((k >> 2) & 31)) << 2) | (q & 3));
}

__global__ __launch_bounds__(256, 1)
void attention_kernel(const float* __restrict__ Q,
                      const float* __restrict__ K,
                      const float* __restrict__ V,
                      const int* __restrict__ mask,
                      float* __restrict__ O)
{
    extern __shared__ float sm[];
    float* Qs = sm;
    float* Ks = sm + 64 * 128;
    float* Vs = sm + 2 * 64 * 128;
    float* Ps = sm + 3 * 64 * 128;
    int*   msk = (int*)(sm + 3 * 64 * 128 + 128 * 128);

    const int tid = threadIdx.x;
    const int tx  = tid & 15;
    const int ty  = tid >> 4;
    const int qt  = blockIdx.x;   // 0..15
    const int h   = blockIdx.y;   // 0..15
    const int b   = blockIdx.z;   // 0..1
    const int colh = h * HEAD_DIM;
    const size_t base = (size_t)b * SEQ * EMBED;

    const float CEXP = 1.4426950408889634f / 32.0f;  // log2(e)/sqrt(EMBED)

    // Load Q tile: 128 q x 64 d -> d-major swizzled
#pragma unroll
    for (int it = 0; it < 8; it++) {
        int idx = tid + it * 256;       // 0..2047
        int q   = idx >> 4;             // 0..127
        int d0  = (idx & 15) * 4;       // 0..60
        float4 v = *(const float4*)(Q + base + (size_t)(qt * 128 + q) * EMBED + colh + d0);
        Qs[qswz(d0 + 0, q)] = v.x;
        Qs[qswz(d0 + 1, q)] = v.y;
        Qs[qswz(d0 + 2, q)] = v.z;
        Qs[qswz(d0 + 3, q)] = v.w;
    }

    const float NEG_INF = __int_as_float(0xff800000);
    float m_r[8], l_r[8], o_r[8][4];
#pragma unroll
    for (int i = 0; i < 8; i++) {
        m_r[i] = NEG_INF;
        l_r[i] = 0.0f;
#pragma unroll
        for (int j = 0; j < 4; j++) o_r[i][j] = 0.0f;
    }

    for (int kt = 0; kt < SEQ / 128; kt++) {
        __syncthreads();   // previous tile fully consumed

        // Load K (d-major swizzled), V (k-major), mask
#pragma unroll
        for (int it = 0; it < 8; it++) {
            int idx = tid + it * 256;
            int k   = idx >> 4;
            int d0  = (idx & 15) * 4;
            size_t goff = base + (size_t)(kt * 128 + k) * EMBED + colh + d0;
            float4 kv = *(const float4*)(K + goff);
            Ks[qswz(d0 + 0, k)] = kv.x;
            Ks[qswz(d0 + 1, k)] = kv.y;
            Ks[qswz(d0 + 2, k)] = kv.z;
            Ks[qswz(d0 + 3, k)] = kv.w;
            float4 vv = *(const float4*)(V + goff);
            *(float4*)&Vs[k * 64 + d0] = vv;
        }
        if (tid < 128) msk[tid] = mask[b * SEQ + kt * 128 + tid];
        __syncthreads();

        // ---- S = Q K^T  (8x8 register tile per thread over [128q x 128k]) ----
        float s[8][8];
#pragma unroll
        for (int i = 0; i < 8; i++)
#pragma unroll
            for (int j = 0; j < 8; j++) s[i][j] = 0.0f;

#pragma unroll 4
        for (int kk = 0; kk < 64; kk++) {
            const float* qrow = Qs + kk * 128;
            const float* krow = Ks + kk * 128;
            const int sa = kk & 31;
            float4 a0 = *(const float4*)(qrow + (((ty * 2)     ^ sa) << 2));
            float4 a1 = *(const float4*)(qrow + (((ty * 2 + 1) ^ sa) << 2));
            float4 b0 = *(const float4*)(krow + (((tx * 2)     ^ sa) << 2));
            float4 b1 = *(const float4*)(krow + (((tx * 2 + 1) ^ sa) << 2));
            float ar[8] = {a0.x, a0.y, a0.z, a0.w, a1.x, a1.y, a1.z, a1.w};
            float br[8] = {b0.x, b0.y, b0.z, b0.w, b1.x, b1.y, b1.z, b1.w};
#pragma unroll
            for (int i = 0; i < 8; i++)
#pragma unroll
                for (int j = 0; j < 8; j++)
                    s[i][j] += ar[i] * br[j];
        }

        // ---- mask ----
        int mj[8];
#pragma unroll
        for (int j = 0; j < 8; j++) mj[j] = msk[tx * 8 + j];
#pragma unroll
        for (int i = 0; i < 8; i++)
#pragma unroll
            for (int j = 0; j < 8; j++)
                s[i][j] = mj[j] ? s[i][j] : -1e20f;

        // ---- online softmax (rows of 128 keys; row owned by 16 tx-lanes) ----
#pragma unroll
        for (int i = 0; i < 8; i++) {
            float mt = s[i][0];
#pragma unroll
            for (int j = 1; j < 8; j++) mt = fmaxf(mt, s[i][j]);
            mt = fmaxf(mt, __shfl_xor_sync(0xffffffffu, mt, 1));
            mt = fmaxf(mt, __shfl_xor_sync(0xffffffffu, mt, 2));
            mt = fmaxf(mt, __shfl_xor_sync(0xffffffffu, mt, 4));
            mt = fmaxf(mt, __shfl_xor_sync(0xffffffffu, mt, 8));

            float mn   = fmaxf(m_r[i], mt);
            float corr = fast_exp2((m_r[i] - mn) * CEXP);
            m_r[i] = mn;

            float rs = 0.0f;
#pragma unroll
            for (int j = 0; j < 8; j++) {
                s[i][j] = fast_exp2((s[i][j] - mn) * CEXP);
                rs += s[i][j];
            }
            rs += __shfl_xor_sync(0xffffffffu, rs, 1);
            rs += __shfl_xor_sync(0xffffffffu, rs, 2);
            rs += __shfl_xor_sync(0xffffffffu, rs, 4);
            rs += __shfl_xor_sync(0xffffffffu, rs, 8);

            l_r[i] = l_r[i] * corr + rs;
#pragma unroll
            for (int j = 0; j < 4; j++) o_r[i][j] *= corr;
        }

        // ---- write P transposed (k-major, swizzled) ----
#pragma unroll
        for (int i = 0; i < 8; i++)
#pragma unroll
            for (int j = 0; j < 8; j++)
                Ps[pswz(tx * 8 + j, ty * 8 + i)] = s[i][j];
        __syncthreads();

        // ---- O += P V   (8q x 4d register tile per thread over [128q x 64d]) ----
#pragma unroll 4
        for (int kk = 0; kk < 128; kk++) {
            const float* prow = Ps + kk * 128;
            const int sa = (kk >> 2) & 31;
            float4 a0 = *(const float4*)(prow + (((ty * 2)     ^ sa) << 2));
            float4 a1 = *(const float4*)(prow + (((ty * 2 + 1) ^ sa) << 2));
            float4 bv = *(const float4*)(Vs + kk * 64 + tx * 4);
            float ar[8] = {a0.x, a0.y, a0.z, a0.w, a1.x, a1.y, a1.z, a1.w};
#pragma unroll
            for (int i = 0; i < 8; i++) {
                o_r[i][0] += ar[i] * bv.x;
                o_r[i][1] += ar[i] * bv.y;
                o_r[i][2] += ar[i] * bv.z;
                o_r[i][3] += ar[i] * bv.w;
            }
        }
    }

    // ---- epilogue: O /= l, write [token, h*64 + d] ----
#pragma unroll
    for (int i = 0; i < 8; i++) {
        float inv = 1.0f / l_r[i];
        int tok = qt * 128 + ty * 8 + i;
        float4 ov = make_float4(o_r[i][0] * inv, o_r[i][1] * inv,
                                o_r[i][2] * inv, o_r[i][3] * inv);
        *(float4*)(O + base + (size_t)tok * EMBED + colh + tx * 4) = ov;
    }
}

// ---------------------------------------------------------------------------
// Launch
// ---------------------------------------------------------------------------
extern "C" void kernel_launch(void* const* d_in, const int* in_sizes, int n_in,
                              void* d_out, int out_size)
{
    const float* query = (const float*)d_in[0];
    const float* key   = (const float*)d_in[1];
    const float* value = (const float*)d_in[2];
    const int*   mask  = (const int*)  d_in[3];
    const float* Wq    = (const float*)d_in[4];
    const float* bq    = (const float*)d_in[5];
    const float* Wk    = (const float*)d_in[6];
    const float* bk    = (const float*)d_in[7];
    const float* Wv    = (const float*)d_in[8];
    const float* bv    = (const float*)d_in[9];
    const float* Wo    = (const float*)d_in[10];
    const float* bo    = (const float*)d_in[11];
    float* out = (float*)d_out;

    float *dq, *dk, *dv, *dao;
    cudaGetSymbolAddress((void**)&dq,  g_q);
    cudaGetSymbolAddress((void**)&dk,  g_k);
    cudaGetSymbolAddress((void**)&dv,  g_v);
    cudaGetSymbolAddress((void**)&dao, g_ao);

    dim3 gg(EMBED / 128, TOKENS / 128);   // (8, 32)

    gemm_bias_kernel<<<gg, 256>>>(query, Wq, bq, dq, TOKENS, EMBED, EMBED);
    gemm_bias_kernel<<<gg, 256>>>(key,   Wk, bk, dk, TOKENS, EMBED, EMBED);
    gemm_bias_kernel<<<gg, 256>>>(value, Wv, bv, dv, TOKENS, EMBED, EMBED);

    cudaFuncSetAttribute(attention_kernel,
                         cudaFuncAttributeMaxDynamicSharedMemorySize, ATT_SMEM);
    attention_kernel<<<dim3(SEQ / 128, HEADS, BATCH), 256, ATT_SMEM>>>(
        dq, dk, dv, mask, dao);

    gemm_bias_kernel<<<gg, 256>>>(dao, Wo, bo, out, TOKENS, EMBED, EMBED);
}

// round 3
// speedup vs baseline: 1.3429x; 1.3429x over previous
#include <cuda_runtime.h>
#include <cuda_bf16.h>
#include <cstdint>
#include <math.h>

#define EMBED    1024
#define HEADS    16
#define HEAD_DIM 64
#define BATCH    2
#define SEQ      2048
#define TOKENS   (BATCH * SEQ)

// ---------------------------------------------------------------------------
// Scratch (device globals)
// ---------------------------------------------------------------------------
__device__ float g_q [TOKENS * EMBED];
__device__ float g_k [TOKENS * EMBED];
__device__ float g_v [TOKENS * EMBED];
__device__ __nv_bfloat16 g_in_hi[3 * TOKENS * EMBED];
__device__ __nv_bfloat16 g_in_lo[3 * TOKENS * EMBED];
__device__ __nv_bfloat16 g_w_hi [4 * EMBED * EMBED];
__device__ __nv_bfloat16 g_w_lo [4 * EMBED * EMBED];
__device__ __nv_bfloat16 g_ao_hi[TOKENS * EMBED];
__device__ __nv_bfloat16 g_ao_lo[TOKENS * EMBED];

__device__ __forceinline__ uint32_t smem_u32(const void* p) {
    uint32_t a;
    asm("{ .reg .u64 t; cvta.to.shared.u64 t, %1; cvt.u32.u64 %0, t; }"
        : "=r"(a) : "l"(p));
    return a;
}
__device__ __forceinline__ float fast_exp2(float x) {
    float y;
    asm("ex2.approx.f32 %0, %1;" : "=f"(y) : "f"(x));
    return y;
}

#define LDSM4(r, a) \
    asm volatile("ldmatrix.sync.aligned.m8n8.x4.shared.b16 {%0,%1,%2,%3}, [%4];" \
                 : "=r"((r)[0]), "=r"((r)[1]), "=r"((r)[2]), "=r"((r)[3]) : "r"(a))
#define LDSM2(r, a) \
    asm volatile("ldmatrix.sync.aligned.m8n8.x2.shared.b16 {%0,%1}, [%2];" \
                 : "=r"((r)[0]), "=r"((r)[1]) : "r"(a))
#define MMA16816(d, a, b) \
    asm volatile("mma.sync.aligned.m16n8k16.row.col.f32.bf16.bf16.f32 " \
                 "{%0,%1,%2,%3}, {%4,%5,%6,%7}, {%8,%9}, {%0,%1,%2,%3};" \
                 : "+f"((d)[0]), "+f"((d)[1]), "+f"((d)[2]), "+f"((d)[3]) \
                 : "r"((a)[0]), "r"((a)[1]), "r"((a)[2]), "r"((a)[3]), \
                   "r"((b)[0]), "r"((b)[1]))

// ---------------------------------------------------------------------------
// fp32 -> bf16 hi/lo split (pre-pass, memory bound)
// ---------------------------------------------------------------------------
__global__ __launch_bounds__(256)
void cvt_split_kernel(const float4* __restrict__ in,
                      uint2* __restrict__ hi, uint2* __restrict__ lo, int n4)
{
    int i = blockIdx.x * 256 + threadIdx.x;
    if (i >= n4) return;
    float4 v = in[i];
    __nv_bfloat162 h0 = __floats2bfloat162_rn(v.x, v.y);
    __nv_bfloat162 h1 = __floats2bfloat162_rn(v.z, v.w);
    __nv_bfloat162 l0 = __floats2bfloat162_rn(v.x - __bfloat162float(__low2bfloat16(h0)),
                                              v.y - __bfloat162float(__high2bfloat16(h0)));
    __nv_bfloat162 l1 = __floats2bfloat162_rn(v.z - __bfloat162float(__low2bfloat16(h1)),
                                              v.w - __bfloat162float(__high2bfloat16(h1)));
    uint2 H, L;
    H.x = *reinterpret_cast<uint32_t*>(&h0); H.y = *reinterpret_cast<uint32_t*>(&h1);
    L.x = *reinterpret_cast<uint32_t*>(&l0); L.y = *reinterpret_cast<uint32_t*>(&l1);
    hi[i] = H;
    lo[i] = L;
}

// ---------------------------------------------------------------------------
// bf16x3 tensor-core GEMM: C[M,1024] = A @ W^T + bias
// A = Ahi+Alo, W = Whi+Wlo (bf16 planes). 128x128 CTA tile, BK=32,
// 8 warps, warp tile 64x32, mma.sync m16n8k16, double-buffered smem.
//
// smem plane layout (per 128x32 bf16 tile): 2 logical rows per 128B line,
// 16B unit swizzle: byte = (m>>1)*128 + ((((m&1)<<2)|c) ^ ((m>>1)&7))*16
// -> conflict-free ldmatrix (units {c^q} span 0..3 / 4..7 across 8 rows).
// ---------------------------------------------------------------------------
__device__ __forceinline__ uint32_t swz(int m, int c) {
    return (uint32_t)((m >> 1) * 128 + (((((m & 1) << 2) | c) ^ ((m >> 1) & 7)) << 4));
}

#define GEMM_SMEM (2 * 4 * 8192)   // 2 stages x 4 planes x 8KB = 64KB

__global__ __launch_bounds__(256)
void gemm_bf16x3_kernel(const __nv_bfloat16* __restrict__ Ahi_b,
                        const __nv_bfloat16* __restrict__ Alo_b,
                        int strideAz,
                        const __nv_bfloat16* __restrict__ Whi_b,
                        const __nv_bfloat16* __restrict__ Wlo_b,
                        int strideWz,
                        const float* __restrict__ b0, const float* __restrict__ b1,
                        const float* __restrict__ b2,
                        float* __restrict__ C0, float* __restrict__ C1,
                        float* __restrict__ C2)
{
    extern __shared__ char sm[];
    const uint32_t sb = smem_u32(sm);
    const int tid  = threadIdx.x;
    const int wid  = tid >> 5;
    const int lane = tid & 31;

    const int z = blockIdx.z;
    const __nv_bfloat16* Ahi = Ahi_b + (size_t)z * strideAz;
    const __nv_bfloat16* Alo = Alo_b + (size_t)z * strideAz;
    const __nv_bfloat16* Whi = Whi_b + (size_t)z * strideWz;
    const __nv_bfloat16* Wlo = Wlo_b + (size_t)z * strideWz;
    const float* bias = (z == 0) ? b0 : (z == 1) ? b1 : b2;
    float*       C    = (z == 0) ? C0 : (z == 1) ? C1 : C2;

    const int row0 = blockIdx.y * 128;
    const int col0 = blockIdx.x * 128;
    const int wm = (wid & 1) * 64;    // warp m offset
    const int wn = (wid >> 1) * 32;   // warp n offset

    // loader mapping: each thread owns row lm, two 16B k-units (lc, lc+1)
    const int lm = tid >> 1;
    const int lc = (tid & 1) * 2;
    const __nv_bfloat16* gAh = Ahi + (size_t)(row0 + lm) * EMBED + lc * 8;
    const __nv_bfloat16* gAl = Alo + (size_t)(row0 + lm) * EMBED + lc * 8;
    const __nv_bfloat16* gWh = Whi + (size_t)(col0 + lm) * EMBED + lc * 8;
    const __nv_bfloat16* gWl = Wlo + (size_t)(col0 + lm) * EMBED + lc * 8;
    const uint32_t s0 = swz(lm, lc);
    const uint32_t s1 = swz(lm, lc + 1);

    float acc[4][4][4];
#pragma unroll
    for (int i = 0; i < 4; i++)
#pragma unroll
        for (int j = 0; j < 4; j++)
#pragma unroll
            for (int q = 0; q < 4; q++) acc[i][j][q] = 0.0f;

    uint4 pa[2], pal[2], pw[2], pwl[2];
#pragma unroll
    for (int u = 0; u < 2; u++) {
        pa [u] = *(const uint4*)(gAh + u * 8);
        pal[u] = *(const uint4*)(gAl + u * 8);
        pw [u] = *(const uint4*)(gWh + u * 8);
        pwl[u] = *(const uint4*)(gWl + u * 8);
    }
    {
        char* st = sm;   // stage 0
        *(uint4*)(st             + s0) = pa[0];  *(uint4*)(st             + s1) = pa[1];
        *(uint4*)(st +     8192  + s0) = pal[0]; *(uint4*)(st +     8192  + s1) = pal[1];
        *(uint4*)(st + 2 * 8192  + s0) = pw[0];  *(uint4*)(st + 2 * 8192  + s1) = pw[1];
        *(uint4*)(st + 3 * 8192  + s0) = pwl[0]; *(uint4*)(st + 3 * 8192  + s1) = pwl[1];
    }
    __syncthreads();

    // fragment address components (constant per thread)
    const int mA = wm + (lane & 7) + ((lane >> 3) & 1) * 8;   // + i*16
    const int cA = (lane >> 4);                               // + ks*2
    const int nB = wn + (lane & 7);                           // + j*8
    const int cB = ((lane >> 3) & 1);                         // + ks*2

    const int NCHUNK = EMBED / 32;
    for (int ch = 0; ch < NCHUNK; ch++) {
        const int stage = ch & 1;
        const uint32_t stb = sb + stage * 32768;

        if (ch + 1 < NCHUNK) {
            const int ko = (ch + 1) * 32;
#pragma unroll
            for (int u = 0; u < 2; u++) {
                pa [u] = *(const uint4*)(gAh + ko + u * 8);
                pal[u] = *(const uint4*)(gAl + ko + u * 8);
                pw [u] = *(const uint4*)(gWh + ko + u * 8);
                pwl[u] = *(const uint4*)(gWl + ko + u * 8);
            }
        }

#pragma unroll
        for (int ks = 0; ks < 2; ks++) {
            uint32_t ah[4][4], al[4][4], bh[4][2], bl[4][2];
            const int ca = ks * 2 + cA;
            const int cb = ks * 2 + cB;
#pragma unroll
            for (int i = 0; i < 4; i++) {
                LDSM4(ah[i], stb            + swz(mA + i * 16, ca));
                LDSM4(al[i], stb + 8192     + swz(mA + i * 16, ca));
            }
#pragma unroll
            for (int j = 0; j < 4; j++) {
                LDSM2(bh[j], stb + 2 * 8192 + swz(nB + j * 8, cb));
                LDSM2(bl[j], stb + 3 * 8192 + swz(nB + j * 8, cb));
            }
#pragma unroll
            for (int i = 0; i < 4; i++)
#pragma unroll
                for (int j = 0; j < 4; j++) {
                    MMA16816(acc[i][j], ah[i], bh[j]);
                    MMA16816(acc[i][j], al[i], bh[j]);
                    MMA16816(acc[i][j], ah[i], bl[j]);
                }
        }

        if (ch + 1 < NCHUNK) {
            char* st = sm + (stage ^ 1) * 32768;
            *(uint4*)(st            + s0) = pa[0];  *(uint4*)(st            + s1) = pa[1];
            *(uint4*)(st +     8192 + s0) = pal[0]; *(uint4*)(st +     8192 + s1) = pal[1];
            *(uint4*)(st + 2 * 8192 + s0) = pw[0];  *(uint4*)(st + 2 * 8192 + s1) = pw[1];
            *(uint4*)(st + 3 * 8192 + s0) = pwl[0]; *(uint4*)(st + 3 * 8192 + s1) = pwl[1];
        }
        __syncthreads();
    }

    // Epilogue: fragment c0,c1 -> (m, n..n+1); c2,c3 -> (m+8, n..n+1)
    const int mrow = row0 + wm + (lane >> 2);
    const int ncol = col0 + wn + (lane & 3) * 2;
#pragma unroll
    for (int i = 0; i < 4; i++) {
#pragma unroll
        for (int j = 0; j < 4; j++) {
            const int r  = mrow + i * 16;
            const int cn = ncol + j * 8;
            const float bx = bias[cn], by = bias[cn + 1];
            float2 v0 = make_float2(acc[i][j][0] + bx, acc[i][j][1] + by);
            float2 v1 = make_float2(acc[i][j][2] + bx, acc[i][j][3] + by);
            *(float2*)(C + (size_t)r       * EMBED + cn) = v0;
            *(float2*)(C + (size_t)(r + 8) * EMBED + cn) = v1;
        }
    }
}

// ---------------------------------------------------------------------------
// Flash attention, fp32 (proven Round-1 kernel; epilogue now emits bf16 hi/lo)
// ---------------------------------------------------------------------------
#define ATT_SMEM ((3 * 64 * 128 + 128 * 128) * 4 + 128 * 4)

__device__ __forceinline__ int qswz(int d, int q) {
    return d * 128 + ((((q >> 2) ^ (d & 31)) << 2) | (q & 3));
}
__device__ __forceinline__ int pswz(int k, int q) {
    return k * 128 + ((((q >> 2) ^ ((k >> 2) & 31)) << 2) | (q & 3));
}

__global__ __launch_bounds__(256, 1)
void attention_kernel(const float* __restrict__ Q,
                      const float* __restrict__ K,
                      const float* __restrict__ V,
                      const int* __restrict__ mask,
                      __nv_bfloat16* __restrict__ Ohi,
                      __nv_bfloat16* __restrict__ Olo)
{
    extern __shared__ float smf[];
    float* Qs = smf;
    float* Ks = smf + 64 * 128;
    float* Vs = smf + 2 * 64 * 128;
    float* Ps = smf + 3 * 64 * 128;
    int*   msk = (int*)(smf + 3 * 64 * 128 + 128 * 128);

    const int tid = threadIdx.x;
    const int tx  = tid & 15;
    const int ty  = tid >> 4;
    const int qt  = blockIdx.x;
    const int h   = blockIdx.y;
    const int b   = blockIdx.z;
    const int colh = h * HEAD_DIM;
    const size_t base = (size_t)b * SEQ * EMBED;

    const float CEXP = 1.4426950408889634f / 32.0f;

#pragma unroll
    for (int it = 0; it < 8; it++) {
        int idx = tid + it * 256;
        int q   = idx >> 4;
        int d0  = (idx & 15) * 4;
        float4 v = *(const float4*)(Q + base + (size_t)(qt * 128 + q) * EMBED + colh + d0);
        Qs[qswz(d0 + 0, q)] = v.x;
        Qs[qswz(d0 + 1, q)] = v.y;
        Qs[qswz(d0 + 2, q)] = v.z;
        Qs[qswz(d0 + 3, q)] = v.w;
    }

    const float NEG_INF = __int_as_float(0xff800000);
    float m_r[8], l_r[8], o_r[8][4];
#pragma unroll
    for (int i = 0; i < 8; i++) {
        m_r[i] = NEG_INF;
        l_r[i] = 0.0f;
#pragma unroll
        for (int j = 0; j < 4; j++) o_r[i][j] = 0.0f;
    }

    for (int kt = 0; kt < SEQ / 128; kt++) {
        __syncthreads();

#pragma unroll
        for (int it = 0; it < 8; it++) {
            int idx = tid + it * 256;
            int k   = idx >> 4;
            int d0  = (idx & 15) * 4;
            size_t goff = base + (size_t)(kt * 128 + k) * EMBED + colh + d0;
            float4 kv = *(const float4*)(K + goff);
            Ks[qswz(d0 + 0, k)] = kv.x;
            Ks[qswz(d0 + 1, k)] = kv.y;
            Ks[qswz(d0 + 2, k)] = kv.z;
            Ks[qswz(d0 + 3, k)] = kv.w;
            float4 vv = *(const float4*)(V + goff);
            *(float4*)&Vs[k * 64 + d0] = vv;
        }
        if (tid < 128) msk[tid] = mask[b * SEQ + kt * 128 + tid];
        __syncthreads();

        float s[8][8];
#pragma unroll
        for (int i = 0; i < 8; i++)
#pragma unroll
            for (int j = 0; j < 8; j++) s[i][j] = 0.0f;

#pragma unroll 4
        for (int kk = 0; kk < 64; kk++) {
            const float* qrow = Qs + kk * 128;
            const float* krow = Ks + kk * 128;
            const int sa = kk & 31;
            float4 a0 = *(const float4*)(qrow + (((ty * 2)     ^ sa) << 2));
            float4 a1 = *(const float4*)(qrow + (((ty * 2 + 1) ^ sa) << 2));
            float4 b0 = *(const float4*)(krow + (((tx * 2)     ^ sa) << 2));
            float4 b1 = *(const float4*)(krow + (((tx * 2 + 1) ^ sa) << 2));
            float ar[8] = {a0.x, a0.y, a0.z, a0.w, a1.x, a1.y, a1.z, a1.w};
            float br[8] = {b0.x, b0.y, b0.z, b0.w, b1.x, b1.y, b1.z, b1.w};
#pragma unroll
            for (int i = 0; i < 8; i++)
#pragma unroll
                for (int j = 0; j < 8; j++)
                    s[i][j] += ar[i] * br[j];
        }

        int mj[8];
#pragma unroll
        for (int j = 0; j < 8; j++) mj[j] = msk[tx * 8 + j];
#pragma unroll
        for (int i = 0; i < 8; i++)
#pragma unroll
            for (int j = 0; j < 8; j++)
                s[i][j] = mj[j] ? s[i][j] : -1e20f;

#pragma unroll
        for (int i = 0; i < 8; i++) {
            float mt = s[i][0];
#pragma unroll
            for (int j = 1; j < 8; j++) mt = fmaxf(mt, s[i][j]);
            mt = fmaxf(mt, __shfl_xor_sync(0xffffffffu, mt, 1));
            mt = fmaxf(mt, __shfl_xor_sync(0xffffffffu, mt, 2));
            mt = fmaxf(mt, __shfl_xor_sync(0xffffffffu, mt, 4));
            mt = fmaxf(mt, __shfl_xor_sync(0xffffffffu, mt, 8));

            float mn   = fmaxf(m_r[i], mt);
            float corr = fast_exp2((m_r[i] - mn) * CEXP);
            m_r[i] = mn;

            float rs = 0.0f;
#pragma unroll
            for (int j = 0; j < 8; j++) {
                s[i][j] = fast_exp2((s[i][j] - mn) * CEXP);
                rs += s[i][j];
            }
            rs += __shfl_xor_sync(0xffffffffu, rs, 1);
            rs += __shfl_xor_sync(0xffffffffu, rs, 2);
            rs += __shfl_xor_sync(0xffffffffu, rs, 4);
            rs += __shfl_xor_sync(0xffffffffu, rs, 8);

            l_r[i] = l_r[i] * corr + rs;
#pragma unroll
            for (int j = 0; j < 4; j++) o_r[i][j] *= corr;
        }

#pragma unroll
        for (int i = 0; i < 8; i++)
#pragma unroll
            for (int j = 0; j < 8; j++)
                Ps[pswz(tx * 8 + j, ty * 8 + i)] = s[i][j];
        __syncthreads();

#pragma unroll 4
        for (int kk = 0; kk < 128; kk++) {
            const float* prow = Ps + kk * 128;
            const int sa = (kk >> 2) & 31;
            float4 a0 = *(const float4*)(prow + (((ty * 2)     ^ sa) << 2));
            float4 a1 = *(const float4*)(prow + (((ty * 2 + 1) ^ sa) << 2));
            float4 bv = *(const float4*)(Vs + kk * 64 + tx * 4);
            float ar[8] = {a0.x, a0.y, a0.z, a0.w, a1.x, a1.y, a1.z, a1.w};
#pragma unroll
            for (int i = 0; i < 8; i++) {
                o_r[i][0] += ar[i] * bv.x;
                o_r[i][1] += ar[i] * bv.y;
                o_r[i][2] += ar[i] * bv.z;
                o_r[i][3] += ar[i] * bv.w;
            }
        }
    }

    // epilogue: normalize and emit bf16 hi/lo split for the output projection
#pragma unroll
    for (int i = 0; i < 8; i++) {
        float inv = 1.0f / l_r[i];
        int tok = qt * 128 + ty * 8 + i;
        float4 ov = make_float4(o_r[i][0] * inv, o_r[i][1] * inv,
                                o_r[i][2] * inv, o_r[i][3] * inv);
        size_t idx = base + (size_t)tok * EMBED + colh + tx * 4;
        __nv_bfloat162 h0 = __floats2bfloat162_rn(ov.x, ov.y);
        __nv_bfloat162 h1 = __floats2bfloat162_rn(ov.z, ov.w);
        __nv_bfloat162 l0 = __floats2bfloat162_rn(
            ov.x - __bfloat162float(__low2bfloat16(h0)),
            ov.y - __bfloat162float(__high2bfloat16(h0)));
        __nv_bfloat162 l1 = __floats2bfloat162_rn(
            ov.z - __bfloat162float(__low2bfloat16(h1)),
            ov.w - __bfloat162float(__high2bfloat16(h1)));
        uint2 H, L;
        H.x = *reinterpret_cast<uint32_t*>(&h0); H.y = *reinterpret_cast<uint32_t*>(&h1);
        L.x = *reinterpret_cast<uint32_t*>(&l0); L.y = *reinterpret_cast<uint32_t*>(&l1);
        *(uint2*)(Ohi + idx) = H;
        *(uint2*)(Olo + idx) = L;
    }
}

// ---------------------------------------------------------------------------
// Launch
// ---------------------------------------------------------------------------
extern "C" void kernel_launch(void* const* d_in, const int* in_sizes, int n_in,
                              void* d_out, int out_size)
{
    const float* query = (const float*)d_in[0];
    const float* key   = (const float*)d_in[1];
    const float* value = (const float*)d_in[2];
    const int*   mask  = (const int*)  d_in[3];
    const float* Wq    = (const float*)d_in[4];
    const float* bq    = (const float*)d_in[5];
    const float* Wk    = (const float*)d_in[6];
    const float* bk    = (const float*)d_in[7];
    const float* Wv    = (const float*)d_in[8];
    const float* bv    = (const float*)d_in[9];
    const float* Wo    = (const float*)d_in[10];
    const float* bo    = (const float*)d_in[11];
    float* out = (float*)d_out;

    float *dq, *dk, *dv;
    __nv_bfloat16 *ih, *il, *wh, *wl, *aoh, *aol;
    cudaGetSymbolAddress((void**)&dq,  g_q);
    cudaGetSymbolAddress((void**)&dk,  g_k);
    cudaGetSymbolAddress((void**)&dv,  g_v);
    cudaGetSymbolAddress((void**)&ih,  g_in_hi);
    cudaGetSymbolAddress((void**)&il,  g_in_lo);
    cudaGetSymbolAddress((void**)&wh,  g_w_hi);
    cudaGetSymbolAddress((void**)&wl,  g_w_lo);
    cudaGetSymbolAddress((void**)&aoh, g_ao_hi);
    cudaGetSymbolAddress((void**)&aol, g_ao_lo);

    cudaFuncSetAttribute(gemm_bf16x3_kernel,
                         cudaFuncAttributeMaxDynamicSharedMemorySize, GEMM_SMEM);
    cudaFuncSetAttribute(attention_kernel,
                         cudaFuncAttributeMaxDynamicSharedMemorySize, ATT_SMEM);

    // Split pre-pass: inputs (q,k,v) and all four weights into bf16 hi/lo
    const int NIN4 = TOKENS * EMBED / 4;   // float4 count per input tensor
    const int NW4  = EMBED * EMBED / 4;
    const float* ins[3] = {query, key, value};
    for (int z = 0; z < 3; z++)
        cvt_split_kernel<<<NIN4 / 256, 256>>>(
            (const float4*)ins[z],
            (uint2*)(ih + (size_t)z * TOKENS * EMBED),
            (uint2*)(il + (size_t)z * TOKENS * EMBED), NIN4);
    const float* ws[4] = {Wq, Wk, Wv, Wo};
    for (int w = 0; w < 4; w++)
        cvt_split_kernel<<<NW4 / 256, 256>>>(
            (const float4*)ws[w],
            (uint2*)(wh + (size_t)w * EMBED * EMBED),
            (uint2*)(wl + (size_t)w * EMBED * EMBED), NW4);

    // QKV projections (z selects input/weight/bias/output)
    gemm_bf16x3_kernel<<<dim3(EMBED / 128, TOKENS / 128, 3), 256, GEMM_SMEM>>>(
        ih, il, TOKENS * EMBED, wh, wl, EMBED * EMBED,
        bq, bk, bv, dq, dk, dv);

    attention_kernel<<<dim3(SEQ / 128, HEADS, BATCH), 256, ATT_SMEM>>>(
        dq, dk, dv, mask, aoh, aol);

    // Output projection (attention epilogue already produced hi/lo A planes)
    gemm_bf16x3_kernel<<<dim3(EMBED / 128, TOKENS / 128, 1), 256, GEMM_SMEM>>>(
        aoh, aol, 0, wh + (size_t)3 * EMBED * EMBED, wl + (size_t)3 * EMBED * EMBED, 0,
        bo, bo, bo, out, out, out);
}

// round 4
// speedup vs baseline: 2.7746x; 2.0662x over previous
#include <cuda_runtime.h>
#include <cuda_bf16.h>
#include <cstdint>
#include <math.h>

#define EMBED    1024
#define HEADS    16
#define HEAD_DIM 64
#define BATCH    2
#define SEQ      2048
#define TOKENS   (BATCH * SEQ)

// ---------------------------------------------------------------------------
// Scratch (device globals)
// ---------------------------------------------------------------------------
__device__ __nv_bfloat16 g_in_hi[3 * TOKENS * EMBED];
__device__ __nv_bfloat16 g_in_lo[3 * TOKENS * EMBED];
__device__ __nv_bfloat16 g_w_hi [4 * EMBED * EMBED];
__device__ __nv_bfloat16 g_w_lo [4 * EMBED * EMBED];
__device__ __nv_bfloat16 g_qh[TOKENS * EMBED], g_ql[TOKENS * EMBED];
__device__ __nv_bfloat16 g_kh[TOKENS * EMBED], g_kl[TOKENS * EMBED];
__device__ __nv_bfloat16 g_vh[TOKENS * EMBED], g_vl[TOKENS * EMBED];
__device__ __nv_bfloat16 g_ao_hi[TOKENS * EMBED];
__device__ __nv_bfloat16 g_ao_lo[TOKENS * EMBED];

__device__ __forceinline__ uint32_t smem_u32(const void* p) {
    uint32_t a;
    asm("{ .reg .u64 t; cvta.to.shared.u64 t, %1; cvt.u32.u64 %0, t; }"
        : "=r"(a) : "l"(p));
    return a;
}
__device__ __forceinline__ float fast_exp2(float x) {
    float y;
    asm("ex2.approx.f32 %0, %1;" : "=f"(y) : "f"(x));
    return y;
}
// pack two floats into bf16x2 hi plane, return lo plane via ref
__device__ __forceinline__ uint32_t split2(float a, float b, uint32_t& lo) {
    __nv_bfloat162 h = __floats2bfloat162_rn(a, b);
    __nv_bfloat162 l = __floats2bfloat162_rn(
        a - __bfloat162float(__low2bfloat16(h)),
        b - __bfloat162float(__high2bfloat16(h)));
    lo = *reinterpret_cast<uint32_t*>(&l);
    return *reinterpret_cast<uint32_t*>(&h);
}

#define LDSM4(r, a) \
    asm volatile("ldmatrix.sync.aligned.m8n8.x4.shared.b16 {%0,%1,%2,%3}, [%4];" \
                 : "=r"((r)[0]), "=r"((r)[1]), "=r"((r)[2]), "=r"((r)[3]) : "r"(a))
#define LDSM4T(r, a) \
    asm volatile("ldmatrix.sync.aligned.m8n8.x4.trans.shared.b16 {%0,%1,%2,%3}, [%4];" \
                 : "=r"((r)[0]), "=r"((r)[1]), "=r"((r)[2]), "=r"((r)[3]) : "r"(a))
#define LDSM2(r, a) \
    asm volatile("ldmatrix.sync.aligned.m8n8.x2.shared.b16 {%0,%1}, [%2];" \
                 : "=r"((r)[0]), "=r"((r)[1]) : "r"(a))
#define MMA16816(d, a, b) \
    asm volatile("mma.sync.aligned.m16n8k16.row.col.f32.bf16.bf16.f32 " \
                 "{%0,%1,%2,%3}, {%4,%5,%6,%7}, {%8,%9}, {%0,%1,%2,%3};" \
                 : "+f"((d)[0]), "+f"((d)[1]), "+f"((d)[2]), "+f"((d)[3]) \
                 : "r"((a)[0]), "r"((a)[1]), "r"((a)[2]), "r"((a)[3]), \
                   "r"((b)[0]), "r"((b)[1]))

// ---------------------------------------------------------------------------
// fp32 -> bf16 hi/lo split (pre-pass, memory bound)
// ---------------------------------------------------------------------------
__global__ __launch_bounds__(256)
void cvt_split_kernel(const float4* __restrict__ in,
                      uint2* __restrict__ hi, uint2* __restrict__ lo, int n4)
{
    int i = blockIdx.x * 256 + threadIdx.x;
    if (i >= n4) return;
    float4 v = in[i];
    uint2 H, L;
    H.x = split2(v.x, v.y, L.x);
    H.y = split2(v.z, v.w, L.y);
    hi[i] = H;
    lo[i] = L;
}

// ---------------------------------------------------------------------------
// bf16x3 tensor-core GEMM: C = A @ W^T + bias. 128x128 CTA, BK=32, 8 warps.
// If H0 != null, output is written as bf16 hi/lo planes instead of fp32.
// ---------------------------------------------------------------------------
__device__ __forceinline__ uint32_t swz(int m, int c) {
    return (uint32_t)((m >> 1) * 128 + (((((m & 1) << 2) | c) ^ ((m >> 1) & 7)) << 4));
}

#define GEMM_SMEM (2 * 4 * 8192)

__global__ __launch_bounds__(256)
void gemm_bf16x3_kernel(const __nv_bfloat16* __restrict__ Ahi_b,
                        const __nv_bfloat16* __restrict__ Alo_b,
                        int strideAz,
                        const __nv_bfloat16* __restrict__ Whi_b,
                        const __nv_bfloat16* __restrict__ Wlo_b,
                        int strideWz,
                        const float* __restrict__ b0, const float* __restrict__ b1,
                        const float* __restrict__ b2,
                        float* __restrict__ Cf,
                        __nv_bfloat16* __restrict__ H0, __nv_bfloat16* __restrict__ H1,
                        __nv_bfloat16* __restrict__ H2,
                        __nv_bfloat16* __restrict__ L0, __nv_bfloat16* __restrict__ L1,
                        __nv_bfloat16* __restrict__ L2)
{
    extern __shared__ char sm[];
    const uint32_t sb = smem_u32(sm);
    const int tid  = threadIdx.x;
    const int wid  = tid >> 5;
    const int lane = tid & 31;

    const int z = blockIdx.z;
    const __nv_bfloat16* Ahi = Ahi_b + (size_t)z * strideAz;
    const __nv_bfloat16* Alo = Alo_b + (size_t)z * strideAz;
    const __nv_bfloat16* Whi = Whi_b + (size_t)z * strideWz;
    const __nv_bfloat16* Wlo = Wlo_b + (size_t)z * strideWz;
    const float* bias = (z == 0) ? b0 : (z == 1) ? b1 : b2;

    const int row0 = blockIdx.y * 128;
    const int col0 = blockIdx.x * 128;
    const int wm = (wid & 1) * 64;
    const int wn = (wid >> 1) * 32;

    const int lm = tid >> 1;
    const int lc = (tid & 1) * 2;
    const __nv_bfloat16* gAh = Ahi + (size_t)(row0 + lm) * EMBED + lc * 8;
    const __nv_bfloat16* gAl = Alo + (size_t)(row0 + lm) * EMBED + lc * 8;
    const __nv_bfloat16* gWh = Whi + (size_t)(col0 + lm) * EMBED + lc * 8;
    const __nv_bfloat16* gWl = Wlo + (size_t)(col0 + lm) * EMBED + lc * 8;
    const uint32_t s0 = swz(lm, lc);
    const uint32_t s1 = swz(lm, lc + 1);

    float acc[4][4][4];
#pragma unroll
    for (int i = 0; i < 4; i++)
#pragma unroll
        for (int j = 0; j < 4; j++)
#pragma unroll
            for (int q = 0; q < 4; q++) acc[i][j][q] = 0.0f;

    uint4 pa[2], pal[2], pw[2], pwl[2];
#pragma unroll
    for (int u = 0; u < 2; u++) {
        pa [u] = *(const uint4*)(gAh + u * 8);
        pal[u] = *(const uint4*)(gAl + u * 8);
        pw [u] = *(const uint4*)(gWh + u * 8);
        pwl[u] = *(const uint4*)(gWl + u * 8);
    }
    {
        char* st = sm;
        *(uint4*)(st            + s0) = pa[0];  *(uint4*)(st            + s1) = pa[1];
        *(uint4*)(st +     8192 + s0) = pal[0]; *(uint4*)(st +     8192 + s1) = pal[1];
        *(uint4*)(st + 2 * 8192 + s0) = pw[0];  *(uint4*)(st + 2 * 8192 + s1) = pw[1];
        *(uint4*)(st + 3 * 8192 + s0) = pwl[0]; *(uint4*)(st + 3 * 8192 + s1) = pwl[1];
    }
    __syncthreads();

    const int mA = wm + (lane & 7) + ((lane >> 3) & 1) * 8;
    const int cA = (lane >> 4);
    const int nB = wn + (lane & 7);
    const int cB = ((lane >> 3) & 1);

    const int NCHUNK = EMBED / 32;
    for (int ch = 0; ch < NCHUNK; ch++) {
        const int stage = ch & 1;
        const uint32_t stb = sb + stage * 32768;

        if (ch + 1 < NCHUNK) {
            const int ko = (ch + 1) * 32;
#pragma unroll
            for (int u = 0; u < 2; u++) {
                pa [u] = *(const uint4*)(gAh + ko + u * 8);
                pal[u] = *(const uint4*)(gAl + ko + u * 8);
                pw [u] = *(const uint4*)(gWh + ko + u * 8);
                pwl[u] = *(const uint4*)(gWl + ko + u * 8);
            }
        }

#pragma unroll
        for (int ks = 0; ks < 2; ks++) {
            uint32_t ah[4][4], al[4][4], bh[4][2], bl[4][2];
            const int ca = ks * 2 + cA;
            const int cb = ks * 2 + cB;
#pragma unroll
            for (int i = 0; i < 4; i++) {
                LDSM4(ah[i], stb        + swz(mA + i * 16, ca));
                LDSM4(al[i], stb + 8192 + swz(mA + i * 16, ca));
            }
#pragma unroll
            for (int j = 0; j < 4; j++) {
                LDSM2(bh[j], stb + 2 * 8192 + swz(nB + j * 8, cb));
                LDSM2(bl[j], stb + 3 * 8192 + swz(nB + j * 8, cb));
            }
#pragma unroll
            for (int i = 0; i < 4; i++)
#pragma unroll
                for (int j = 0; j < 4; j++) {
                    MMA16816(acc[i][j], ah[i], bh[j]);
                    MMA16816(acc[i][j], al[i], bh[j]);
                    MMA16816(acc[i][j], ah[i], bl[j]);
                }
        }

        if (ch + 1 < NCHUNK) {
            char* st = sm + (stage ^ 1) * 32768;
            *(uint4*)(st            + s0) = pa[0];  *(uint4*)(st            + s1) = pa[1];
            *(uint4*)(st +     8192 + s0) = pal[0]; *(uint4*)(st +     8192 + s1) = pal[1];
            *(uint4*)(st + 2 * 8192 + s0) = pw[0];  *(uint4*)(st + 2 * 8192 + s1) = pw[1];
            *(uint4*)(st + 3 * 8192 + s0) = pwl[0]; *(uint4*)(st + 3 * 8192 + s1) = pwl[1];
        }
        __syncthreads();
    }

    const int mrow = row0 + wm + (lane >> 2);
    const int ncol = col0 + wn + (lane & 3) * 2;
    if (H0) {
        __nv_bfloat16* Hi = (z == 0) ? H0 : (z == 1) ? H1 : H2;
        __nv_bfloat16* Lo = (z == 0) ? L0 : (z == 1) ? L1 : L2;
#pragma unroll
        for (int i = 0; i < 4; i++)
#pragma unroll
            for (int j = 0; j < 4; j++) {
                const int r  = mrow + i * 16;
                const int cn = ncol + j * 8;
                const float bx = bias[cn], by = bias[cn + 1];
                uint32_t l0v, l1v;
                uint32_t h0v = split2(acc[i][j][0] + bx, acc[i][j][1] + by, l0v);
                uint32_t h1v = split2(acc[i][j][2] + bx, acc[i][j][3] + by, l1v);
                *(uint32_t*)(Hi + (size_t)r       * EMBED + cn) = h0v;
                *(uint32_t*)(Lo + (size_t)r       * EMBED + cn) = l0v;
                *(uint32_t*)(Hi + (size_t)(r + 8) * EMBED + cn) = h1v;
                *(uint32_t*)(Lo + (size_t)(r + 8) * EMBED + cn) = l1v;
            }
    } else {
#pragma unroll
        for (int i = 0; i < 4; i++)
#pragma unroll
            for (int j = 0; j < 4; j++) {
                const int r  = mrow + i * 16;
                const int cn = ncol + j * 8;
                const float bx = bias[cn], by = bias[cn + 1];
                float2 v0 = make_float2(acc[i][j][0] + bx, acc[i][j][1] + by);
                float2 v1 = make_float2(acc[i][j][2] + bx, acc[i][j][3] + by);
                *(float2*)(Cf + (size_t)r       * EMBED + cn) = v0;
                *(float2*)(Cf + (size_t)(r + 8) * EMBED + cn) = v1;
            }
    }
}

// ---------------------------------------------------------------------------
// Tensor-core flash attention (bf16x3).
// CTA = 128 q rows x (b, h). 8 warps, warp tile 16q x 128k (softmax warp-local).
// Q/K/V smem: [row][64d] bf16, 128B rows, XOR-swizzled 16B units.
// S = QKt: A-frags from Q (LDSM4), B-frags from K (LDSM4).
// P kept in registers as A-frags (hi/lo). O += P V: B-frags via LDSM4T on V[k][d].
// ---------------------------------------------------------------------------
#define ATT_SMEM (6 * 16384 + 512)

__global__ __launch_bounds__(256, 1)
void attention_tc_kernel(const __nv_bfloat16* __restrict__ Qh,
                         const __nv_bfloat16* __restrict__ Ql,
                         const __nv_bfloat16* __restrict__ Kh,
                         const __nv_bfloat16* __restrict__ Kl,
                         const __nv_bfloat16* __restrict__ Vh,
                         const __nv_bfloat16* __restrict__ Vl,
                         const int* __restrict__ mask,
                         __nv_bfloat16* __restrict__ Ohi,
                         __nv_bfloat16* __restrict__ Olo)
{
    extern __shared__ char sm[];
    const uint32_t sb = smem_u32(sm);
    const uint32_t oQh = 0, oQl = 16384, oKh = 32768, oKl = 49152,
                   oVh = 65536, oVl = 81920, oM = 98304;
    const int tid  = threadIdx.x;
    const int lane = tid & 31;
    const int w    = tid >> 5;
    const int qt   = blockIdx.x;
    const int h    = blockIdx.y;
    const int b    = blockIdx.z;
    const int colh = h * HEAD_DIM;
    const size_t base = (size_t)b * SEQ * EMBED;
    const float CEXP = 1.4426950408889634f / 32.0f;   // log2(e)/sqrt(EMBED)
    const int* msk = (const int*)(sm + oM);

    // Load Q tile (both planes): row-major [128][64] bf16, swizzled
#pragma unroll
    for (int it = 0; it < 4; it++) {
        int idx = tid + it * 256;           // 0..1023
        int r = idx >> 3, u = idx & 7;
        size_t g = base + (size_t)(qt * 128 + r) * EMBED + colh + u * 8;
        uint32_t so = (uint32_t)(r * 128 + ((u ^ (r & 7)) << 4));
        *(uint4*)(sm + oQh + so) = *(const uint4*)(Qh + g);
        *(uint4*)(sm + oQl + so) = *(const uint4*)(Ql + g);
    }

    const int q0 = w * 16;
    float o[8][4];
#pragma unroll
    for (int j = 0; j < 8; j++)
#pragma unroll
        for (int q = 0; q < 4; q++) o[j][q] = 0.0f;
    const float NEG_INF = __int_as_float(0xff800000);
    float mr0 = NEG_INF, mr1 = NEG_INF, lr0 = 0.0f, lr1 = 0.0f;

    // ldmatrix lane-address components
    const uint32_t rowA = (uint32_t)(q0 + (lane & 15));          // A (Q)
    const uint32_t uA   = (uint32_t)(lane >> 4);
    const uint32_t rowB = (uint32_t)((lane & 7) + ((lane >> 4) << 3));   // B (K)
    const uint32_t uB   = (uint32_t)((lane >> 3) & 1);
    const uint32_t rowV = (uint32_t)((lane & 7) + (((lane >> 3) & 1) << 3)); // B (V, trans)
    const uint32_t uV   = (uint32_t)(lane >> 4);

    for (int kt = 0; kt < 16; kt++) {
        __syncthreads();
#pragma unroll
        for (int it = 0; it < 4; it++) {
            int idx = tid + it * 256;
            int r = idx >> 3, u = idx & 7;
            size_t g = base + (size_t)(kt * 128 + r) * EMBED + colh + u * 8;
            uint32_t so = (uint32_t)(r * 128 + ((u ^ (r & 7)) << 4));
            *(uint4*)(sm + oKh + so) = *(const uint4*)(Kh + g);
            *(uint4*)(sm + oKl + so) = *(const uint4*)(Kl + g);
            *(uint4*)(sm + oVh + so) = *(const uint4*)(Vh + g);
            *(uint4*)(sm + oVl + so) = *(const uint4*)(Vl + g);
        }
        if (tid < 128) ((int*)(sm + oM))[tid] = mask[b * SEQ + kt * 128 + tid];
        __syncthreads();

        // ---- S = Q K^T : 16 n8-tiles of fp32 frags per warp ----
        float s[16][4];
#pragma unroll
        for (int j = 0; j < 16; j++)
#pragma unroll
            for (int q = 0; q < 4; q++) s[j][q] = 0.0f;

#pragma unroll
        for (int ks = 0; ks < 4; ks++) {
            uint32_t ah[4], al[4];
            const uint32_t ua = uA + ks * 2;
            const uint32_t aoff = rowA * 128 + ((ua ^ (rowA & 7)) << 4);
            LDSM4(ah, sb + oQh + aoff);
            LDSM4(al, sb + oQl + aoff);
#pragma unroll
            for (int np = 0; np < 8; np++) {
                const uint32_t rb = rowB + np * 16;
                const uint32_t ub = uB + ks * 2;
                const uint32_t boff = rb * 128 + ((ub ^ (rb & 7)) << 4);
                uint32_t kh4[4], kl4[4];
                LDSM4(kh4, sb + oKh + boff);
                LDSM4(kl4, sb + oKl + boff);
                MMA16816(s[2 * np],     ah, kh4);     // Qh Kh
                MMA16816(s[2 * np],     al, kh4);     // Ql Kh
                MMA16816(s[2 * np],     ah, kl4);     // Qh Kl
                MMA16816(s[2 * np + 1], ah, kh4 + 2);
                MMA16816(s[2 * np + 1], al, kh4 + 2);
                MMA16816(s[2 * np + 1], ah, kl4 + 2);
            }
        }

        // ---- mask + online softmax (rows r0 = lane>>2, r1 = r0+8) ----
        const int cb2 = (lane & 3) * 2;
        float mx0 = NEG_INF, mx1 = NEG_INF;
#pragma unroll
        for (int j = 0; j < 16; j++) {
            const int col = j * 8 + cb2;
            const int m0v = msk[col], m1v = msk[col + 1];
            if (!m0v) { s[j][0] = -1e20f; s[j][2] = -1e20f; }
            if (!m1v) { s[j][1] = -1e20f; s[j][3] = -1e20f; }
            mx0 = fmaxf(mx0, fmaxf(s[j][0], s[j][1]));
            mx1 = fmaxf(mx1, fmaxf(s[j][2], s[j][3]));
        }
        mx0 = fmaxf(mx0, __shfl_xor_sync(0xffffffffu, mx0, 1));
        mx0 = fmaxf(mx0, __shfl_xor_sync(0xffffffffu, mx0, 2));
        mx1 = fmaxf(mx1, __shfl_xor_sync(0xffffffffu, mx1, 1));
        mx1 = fmaxf(mx1, __shfl_xor_sync(0xffffffffu, mx1, 2));

        const float mn0 = fmaxf(mr0, mx0);
        const float mn1 = fmaxf(mr1, mx1);
        const float c0 = fast_exp2((mr0 - mn0) * CEXP);
        const float c1 = fast_exp2((mr1 - mn1) * CEXP);
        mr0 = mn0; mr1 = mn1;

        float sum0 = 0.0f, sum1 = 0.0f;
#pragma unroll
        for (int j = 0; j < 16; j++) {
            s[j][0] = fast_exp2((s[j][0] - mn0) * CEXP);
            s[j][1] = fast_exp2((s[j][1] - mn0) * CEXP);
            s[j][2] = fast_exp2((s[j][2] - mn1) * CEXP);
            s[j][3] = fast_exp2((s[j][3] - mn1) * CEXP);
            sum0 += s[j][0] + s[j][1];
            sum1 += s[j][2] + s[j][3];
        }
        sum0 += __shfl_xor_sync(0xffffffffu, sum0, 1);
        sum0 += __shfl_xor_sync(0xffffffffu, sum0, 2);
        sum1 += __shfl_xor_sync(0xffffffffu, sum1, 1);
        sum1 += __shfl_xor_sync(0xffffffffu, sum1, 2);
        lr0 = lr0 * c0 + sum0;
        lr1 = lr1 * c1 + sum1;
#pragma unroll
        for (int jd = 0; jd < 8; jd++) {
            o[jd][0] *= c0; o[jd][1] *= c0;
            o[jd][2] *= c1; o[jd][3] *= c1;
        }

        // ---- convert S frags -> P A-frags (hi/lo) in registers ----
        uint32_t ph[8][4], pl[8][4];
#pragma unroll
        for (int kk = 0; kk < 8; kk++) {
            ph[kk][0] = split2(s[2 * kk][0],     s[2 * kk][1],     pl[kk][0]);
            ph[kk][1] = split2(s[2 * kk][2],     s[2 * kk][3],     pl[kk][1]);
            ph[kk][2] = split2(s[2 * kk + 1][0], s[2 * kk + 1][1], pl[kk][2]);
            ph[kk][3] = split2(s[2 * kk + 1][2], s[2 * kk + 1][3], pl[kk][3]);
        }

        // ---- O += P V : LDSM4T B-frags from V[k][d] ----
#pragma unroll
        for (int kk = 0; kk < 8; kk++) {
            const uint32_t k0 = kk * 16;
#pragma unroll
            for (int jdp = 0; jdp < 4; jdp++) {
                const uint32_t rv = k0 + rowV;
                const uint32_t uv = jdp * 2 + uV;
                const uint32_t voff = rv * 128 + ((uv ^ (rv & 7)) << 4);
                uint32_t bh4[4], bl4[4];
                LDSM4T(bh4, sb + oVh + voff);
                LDSM4T(bl4, sb + oVl + voff);
                MMA16816(o[2 * jdp],     ph[kk], bh4);
                MMA16816(o[2 * jdp],     pl[kk], bh4);
                MMA16816(o[2 * jdp],     ph[kk], bl4);
                MMA16816(o[2 * jdp + 1], ph[kk], bh4 + 2);
                MMA16816(o[2 * jdp + 1], pl[kk], bh4 + 2);
                MMA16816(o[2 * jdp + 1], ph[kk], bl4 + 2);
            }
        }
    }

    // ---- epilogue: normalize, split bf16 hi/lo, store ----
    const float inv0 = 1.0f / lr0;
    const float inv1 = 1.0f / lr1;
    const int r0g = qt * 128 + q0 + (lane >> 2);
    const int cbe = (lane & 3) * 2;
#pragma unroll
    for (int jd = 0; jd < 8; jd++) {
        const int cn = colh + jd * 8 + cbe;
        uint32_t l0v, l1v;
        uint32_t h0v = split2(o[jd][0] * inv0, o[jd][1] * inv0, l0v);
        uint32_t h1v = split2(o[jd][2] * inv1, o[jd][3] * inv1, l1v);
        size_t i0 = base + (size_t)r0g * EMBED + cn;
        size_t i1 = base + (size_t)(r0g + 8) * EMBED + cn;
        *(uint32_t*)(Ohi + i0) = h0v;
        *(uint32_t*)(Olo + i0) = l0v;
        *(uint32_t*)(Ohi + i1) = h1v;
        *(uint32_t*)(Olo + i1) = l1v;
    }
}

// ---------------------------------------------------------------------------
// Launch
// ---------------------------------------------------------------------------
extern "C" void kernel_launch(void* const* d_in, const int* in_sizes, int n_in,
                              void* d_out, int out_size)
{
    const float* query = (const float*)d_in[0];
    const float* key   = (const float*)d_in[1];
    const float* value = (const float*)d_in[2];
    const int*   mask  = (const int*)  d_in[3];
    const float* Wq    = (const float*)d_in[4];
    const float* bq    = (const float*)d_in[5];
    const float* Wk    = (const float*)d_in[6];
    const float* bk    = (const float*)d_in[7];
    const float* Wv    = (const float*)d_in[8];
    const float* bv    = (const float*)d_in[9];
    const float* Wo    = (const float*)d_in[10];
    const float* bo    = (const float*)d_in[11];
    float* out = (float*)d_out;

    __nv_bfloat16 *ih, *il, *wh, *wl, *aoh, *aol;
    __nv_bfloat16 *qh, *ql, *kh, *kl, *vh, *vl;
    cudaGetSymbolAddress((void**)&ih,  g_in_hi);
    cudaGetSymbolAddress((void**)&il,  g_in_lo);
    cudaGetSymbolAddress((void**)&wh,  g_w_hi);
    cudaGetSymbolAddress((void**)&wl,  g_w_lo);
    cudaGetSymbolAddress((void**)&aoh, g_ao_hi);
    cudaGetSymbolAddress((void**)&aol, g_ao_lo);
    cudaGetSymbolAddress((void**)&qh,  g_qh);
    cudaGetSymbolAddress((void**)&ql,  g_ql);
    cudaGetSymbolAddress((void**)&kh,  g_kh);
    cudaGetSymbolAddress((void**)&kl,  g_kl);
    cudaGetSymbolAddress((void**)&vh,  g_vh);
    cudaGetSymbolAddress((void**)&vl,  g_vl);

    cudaFuncSetAttribute(gemm_bf16x3_kernel,
                         cudaFuncAttributeMaxDynamicSharedMemorySize, GEMM_SMEM);
    cudaFuncSetAttribute(attention_tc_kernel,
                         cudaFuncAttributeMaxDynamicSharedMemorySize, ATT_SMEM);

    // Split pre-pass: inputs and weights -> bf16 hi/lo planes
    const int NIN4 = TOKENS * EMBED / 4;
    const int NW4  = EMBED * EMBED / 4;
    const float* ins[3] = {query, key, value};
    for (int z = 0; z < 3; z++)
        cvt_split_kernel<<<NIN4 / 256, 256>>>(
            (const float4*)ins[z],
            (uint2*)(ih + (size_t)z * TOKENS * EMBED),
            (uint2*)(il + (size_t)z * TOKENS * EMBED), NIN4);
    const float* ws[4] = {Wq, Wk, Wv, Wo};
    for (int w = 0; w < 4; w++)
        cvt_split_kernel<<<NW4 / 256, 256>>>(
            (const float4*)ws[w],
            (uint2*)(wh + (size_t)w * EMBED * EMBED),
            (uint2*)(wl + (size_t)w * EMBED * EMBED), NW4);

    // QKV projections -> bf16 hi/lo planes directly
    gemm_bf16x3_kernel<<<dim3(EMBED / 128, TOKENS / 128, 3), 256, GEMM_SMEM>>>(
        ih, il, TOKENS * EMBED, wh, wl, EMBED * EMBED,
        bq, bk, bv, nullptr, qh, kh, vh, ql, kl, vl);

    // Tensor-core flash attention
    attention_tc_kernel<<<dim3(SEQ / 128, HEADS, BATCH), 256, ATT_SMEM>>>(
        qh, ql, kh, kl, vh, vl, mask, aoh, aol);

    // Output projection -> fp32
    gemm_bf16x3_kernel<<<dim3(EMBED / 128, TOKENS / 128, 1), 256, GEMM_SMEM>>>(
        aoh, aol, 0, wh + (size_t)3 * EMBED * EMBED, wl + (size_t)3 * EMBED * EMBED, 0,
        bo, bo, bo, out,
        nullptr, nullptr, nullptr, nullptr, nullptr, nullptr);
}

// round 5
// speedup vs baseline: 2.9055x; 1.0472x over previous
#include <cuda_runtime.h>
#include <cuda_bf16.h>
#include <cstdint>
#include <math.h>

#define EMBED    1024
#define HEADS    16
#define HEAD_DIM 64
#define BATCH    2
#define SEQ      2048
#define TOKENS   (BATCH * SEQ)

// ---------------------------------------------------------------------------
// Scratch (device globals)
// ---------------------------------------------------------------------------
__device__ __nv_bfloat16 g_in_hi[3 * TOKENS * EMBED];
__device__ __nv_bfloat16 g_in_lo[3 * TOKENS * EMBED];
__device__ __nv_bfloat16 g_w_hi [4 * EMBED * EMBED];
__device__ __nv_bfloat16 g_w_lo [4 * EMBED * EMBED];
__device__ __nv_bfloat16 g_qh[TOKENS * EMBED], g_ql[TOKENS * EMBED];
__device__ __nv_bfloat16 g_kh[TOKENS * EMBED], g_kl[TOKENS * EMBED];
__device__ __nv_bfloat16 g_vh[TOKENS * EMBED], g_vl[TOKENS * EMBED];
__device__ __nv_bfloat16 g_ao_hi[TOKENS * EMBED];
__device__ __nv_bfloat16 g_ao_lo[TOKENS * EMBED];

__device__ __forceinline__ uint32_t smem_u32(const void* p) {
    uint32_t a;
    asm("{ .reg .u64 t; cvta.to.shared.u64 t, %1; cvt.u32.u64 %0, t; }"
        : "=r"(a) : "l"(p));
    return a;
}
__device__ __forceinline__ float fast_exp2(float x) {
    float y;
    asm("ex2.approx.f32 %0, %1;" : "=f"(y) : "f"(x));
    return y;
}
__device__ __forceinline__ uint32_t split2(float a, float b, uint32_t& lo) {
    __nv_bfloat162 h = __floats2bfloat162_rn(a, b);
    __nv_bfloat162 l = __floats2bfloat162_rn(
        a - __bfloat162float(__low2bfloat16(h)),
        b - __bfloat162float(__high2bfloat16(h)));
    lo = *reinterpret_cast<uint32_t*>(&l);
    return *reinterpret_cast<uint32_t*>(&h);
}

#define LDSM4(r, a) \
    asm volatile("ldmatrix.sync.aligned.m8n8.x4.shared.b16 {%0,%1,%2,%3}, [%4];" \
                 : "=r"((r)[0]), "=r"((r)[1]), "=r"((r)[2]), "=r"((r)[3]) : "r"(a))
#define LDSM4T(r, a) \
    asm volatile("ldmatrix.sync.aligned.m8n8.x4.trans.shared.b16 {%0,%1,%2,%3}, [%4];" \
                 : "=r"((r)[0]), "=r"((r)[1]), "=r"((r)[2]), "=r"((r)[3]) : "r"(a))
#define MMA16816(d, a, b) \
    asm volatile("mma.sync.aligned.m16n8k16.row.col.f32.bf16.bf16.f32 " \
                 "{%0,%1,%2,%3}, {%4,%5,%6,%7}, {%8,%9}, {%0,%1,%2,%3};" \
                 : "+f"((d)[0]), "+f"((d)[1]), "+f"((d)[2]), "+f"((d)[3]) \
                 : "r"((a)[0]), "r"((a)[1]), "r"((a)[2]), "r"((a)[3]), \
                   "r"((b)[0]), "r"((b)[1]))
#define CP16(dst, src) \
    asm volatile("cp.async.ca.shared.global [%0], [%1], 16;" \
                 :: "r"(dst), "l"(src) : "memory")
#define CP_COMMIT() asm volatile("cp.async.commit_group;" ::: "memory")
#define CP_WAIT(n)  asm volatile("cp.async.wait_group %0;" :: "n"(n) : "memory")

// ---------------------------------------------------------------------------
// Fused fp32 -> bf16 hi/lo split for 3 inputs + 4 weights (one launch)
// ---------------------------------------------------------------------------
__global__ __launch_bounds__(256)
void cvt_split_all_kernel(const float4* __restrict__ q, const float4* __restrict__ k,
                          const float4* __restrict__ v,
                          const float4* __restrict__ wq, const float4* __restrict__ wk,
                          const float4* __restrict__ wv, const float4* __restrict__ wo,
                          uint2* __restrict__ ih, uint2* __restrict__ il,
                          uint2* __restrict__ wh, uint2* __restrict__ wl)
{
    const int NI = TOKENS * EMBED / 4;   // 1M float4 per input tensor
    const int NW = EMBED * EMBED / 4;    // 256K float4 per weight
    int i = blockIdx.x * 256 + threadIdx.x;

    const float4* src;
    uint2 *H, *L;
    if (i < 3 * NI) {
        int seg = i / NI;
        int off = i - seg * NI;
        src = (seg == 0 ? q : seg == 1 ? k : v) + off;
        H = ih + (size_t)seg * NI + off;
        L = il + (size_t)seg * NI + off;
    } else {
        int j = i - 3 * NI;
        int seg = j / NW;
        int off = j - seg * NW;
        src = (seg == 0 ? wq : seg == 1 ? wk : seg == 2 ? wv : wo) + off;
        H = wh + (size_t)seg * NW + off;
        L = wl + (size_t)seg * NW + off;
    }
    float4 val = *src;
    uint2 Hv, Lv;
    Hv.x = split2(val.x, val.y, Lv.x);
    Hv.y = split2(val.z, val.w, Lv.y);
    *H = Hv;
    *L = Lv;
}

// ---------------------------------------------------------------------------
// bf16x3 tensor-core GEMM: C = A @ W^T + bias. 128x128 CTA, BK=32, 8 warps.
// 3-stage cp.async pipeline, one __syncthreads per chunk.
// ---------------------------------------------------------------------------
__device__ __forceinline__ uint32_t swz(int m, int c) {
    return (uint32_t)((m >> 1) * 128 + (((((m & 1) << 2) | c) ^ ((m >> 1) & 7)) << 4));
}

#define GEMM_SMEM (3 * 4 * 8192)   // 3 stages x 4 planes x 8KB = 96KB

__global__ __launch_bounds__(256)
void gemm_bf16x3_kernel(const __nv_bfloat16* __restrict__ Ahi_b,
                        const __nv_bfloat16* __restrict__ Alo_b,
                        int strideAz,
                        const __nv_bfloat16* __restrict__ Whi_b,
                        const __nv_bfloat16* __restrict__ Wlo_b,
                        int strideWz,
                        const float* __restrict__ b0, const float* __restrict__ b1,
                        const float* __restrict__ b2,
                        float* __restrict__ Cf,
                        __nv_bfloat16* __restrict__ H0, __nv_bfloat16* __restrict__ H1,
                        __nv_bfloat16* __restrict__ H2,
                        __nv_bfloat16* __restrict__ L0, __nv_bfloat16* __restrict__ L1,
                        __nv_bfloat16* __restrict__ L2)
{
    extern __shared__ char sm[];
    const uint32_t sb = smem_u32(sm);
    const int tid  = threadIdx.x;
    const int wid  = tid >> 5;
    const int lane = tid & 31;

    const int z = blockIdx.z;
    const __nv_bfloat16* Ahi = Ahi_b + (size_t)z * strideAz;
    const __nv_bfloat16* Alo = Alo_b + (size_t)z * strideAz;
    const __nv_bfloat16* Whi = Whi_b + (size_t)z * strideWz;
    const __nv_bfloat16* Wlo = Wlo_b + (size_t)z * strideWz;
    const float* bias = (z == 0) ? b0 : (z == 1) ? b1 : b2;

    const int row0 = blockIdx.y * 128;
    const int col0 = blockIdx.x * 128;
    const int wm = (wid & 1) * 64;
    const int wn = (wid >> 1) * 32;

    const int lm = tid >> 1;
    const int lc = (tid & 1) * 2;
    const __nv_bfloat16* gAh = Ahi + (size_t)(row0 + lm) * EMBED + lc * 8;
    const __nv_bfloat16* gAl = Alo + (size_t)(row0 + lm) * EMBED + lc * 8;
    const __nv_bfloat16* gWh = Whi + (size_t)(col0 + lm) * EMBED + lc * 8;
    const __nv_bfloat16* gWl = Wlo + (size_t)(col0 + lm) * EMBED + lc * 8;
    const uint32_t s0 = swz(lm, lc);
    const uint32_t s1 = swz(lm, lc + 1);

    float acc[4][4][4];
#pragma unroll
    for (int i = 0; i < 4; i++)
#pragma unroll
        for (int j = 0; j < 4; j++)
#pragma unroll
            for (int q = 0; q < 4; q++) acc[i][j][q] = 0.0f;

    // cp.async issue for chunk ch into stage ch%3
    auto issue = [&](int ch) {
        const uint32_t st = sb + (uint32_t)(ch % 3) * 32768u;
        const int ko = ch * 32;
        CP16(st             + s0, gAh + ko);
        CP16(st             + s1, gAh + ko + 8);
        CP16(st +     8192u + s0, gAl + ko);
        CP16(st +     8192u + s1, gAl + ko + 8);
        CP16(st + 2 * 8192u + s0, gWh + ko);
        CP16(st + 2 * 8192u + s1, gWh + ko + 8);
        CP16(st + 3 * 8192u + s0, gWl + ko);
        CP16(st + 3 * 8192u + s1, gWl + ko + 8);
    };

    issue(0); CP_COMMIT();
    issue(1); CP_COMMIT();

    // fragment address components
    const int mA  = wm + (lane & 7) + ((lane >> 3) & 1) * 8;
    const int cA  = (lane >> 4);
    const int nB4 = wn + (lane & 7) + ((lane >> 4) << 3);   // x4 B: lanes 16-31 -> +8 rows
    const int cB4 = ((lane >> 3) & 1);

    const int NCHUNK = EMBED / 32;   // 32
    for (int ch = 0; ch < NCHUNK; ch++) {
        if (ch + 1 < NCHUNK) { CP_WAIT(1); } else { CP_WAIT(0); }
        __syncthreads();
        if (ch + 2 < NCHUNK) { issue(ch + 2); CP_COMMIT(); }

        const uint32_t stb = sb + (uint32_t)(ch % 3) * 32768u;
#pragma unroll
        for (int ks = 0; ks < 2; ks++) {
            uint32_t ah[4][4], al[4][4], bh[4][2], bl[4][2];
            const int ca = ks * 2 + cA;
            const int cb = ks * 2 + cB4;
#pragma unroll
            for (int i = 0; i < 4; i++) {
                LDSM4(ah[i], stb        + swz(mA + i * 16, ca));
                LDSM4(al[i], stb + 8192 + swz(mA + i * 16, ca));
            }
#pragma unroll
            for (int jj = 0; jj < 2; jj++) {
                uint32_t t[4];
                LDSM4(t, stb + 2 * 8192 + swz(nB4 + jj * 16, cb));
                bh[2 * jj][0] = t[0]; bh[2 * jj][1] = t[1];
                bh[2 * jj + 1][0] = t[2]; bh[2 * jj + 1][1] = t[3];
                LDSM4(t, stb + 3 * 8192 + swz(nB4 + jj * 16, cb));
                bl[2 * jj][0] = t[0]; bl[2 * jj][1] = t[1];
                bl[2 * jj + 1][0] = t[2]; bl[2 * jj + 1][1] = t[3];
            }
#pragma unroll
            for (int i = 0; i < 4; i++)
#pragma unroll
                for (int j = 0; j < 4; j++) {
                    MMA16816(acc[i][j], ah[i], bh[j]);
                    MMA16816(acc[i][j], al[i], bh[j]);
                    MMA16816(acc[i][j], ah[i], bl[j]);
                }
        }
    }

    const int mrow = row0 + wm + (lane >> 2);
    const int ncol = col0 + wn + (lane & 3) * 2;
    if (H0) {
        __nv_bfloat16* Hi = (z == 0) ? H0 : (z == 1) ? H1 : H2;
        __nv_bfloat16* Lo = (z == 0) ? L0 : (z == 1) ? L1 : L2;
#pragma unroll
        for (int i = 0; i < 4; i++)
#pragma unroll
            for (int j = 0; j < 4; j++) {
                const int r  = mrow + i * 16;
                const int cn = ncol + j * 8;
                const float bx = bias[cn], by = bias[cn + 1];
                uint32_t l0v, l1v;
                uint32_t h0v = split2(acc[i][j][0] + bx, acc[i][j][1] + by, l0v);
                uint32_t h1v = split2(acc[i][j][2] + bx, acc[i][j][3] + by, l1v);
                *(uint32_t*)(Hi + (size_t)r       * EMBED + cn) = h0v;
                *(uint32_t*)(Lo + (size_t)r       * EMBED + cn) = l0v;
                *(uint32_t*)(Hi + (size_t)(r + 8) * EMBED + cn) = h1v;
                *(uint32_t*)(Lo + (size_t)(r + 8) * EMBED + cn) = l1v;
            }
    } else {
#pragma unroll
        for (int i = 0; i < 4; i++)
#pragma unroll
            for (int j = 0; j < 4; j++) {
                const int r  = mrow + i * 16;
                const int cn = ncol + j * 8;
                const float bx = bias[cn], by = bias[cn + 1];
                float2 v0 = make_float2(acc[i][j][0] + bx, acc[i][j][1] + by);
                float2 v1 = make_float2(acc[i][j][2] + bx, acc[i][j][3] + by);
                *(float2*)(Cf + (size_t)r       * EMBED + cn) = v0;
                *(float2*)(Cf + (size_t)(r + 8) * EMBED + cn) = v1;
            }
    }
}

// ---------------------------------------------------------------------------
// Tensor-core flash attention (bf16x3), 2-stage cp.async K/V double buffer.
// CTA = 128 q x (b,h). 8 warps, warp tile 16q x 128k.
// smem: Qh(16K) Ql(16K) | stage s: Kh Kl Vh Vl (16K each) + mask(512B)
// ---------------------------------------------------------------------------
#define ATT_STAGE (4 * 16384 + 512)
#define ATT_SMEM  (2 * 16384 + 2 * ATT_STAGE)

__global__ __launch_bounds__(256, 1)
void attention_tc_kernel(const __nv_bfloat16* __restrict__ Qh,
                         const __nv_bfloat16* __restrict__ Ql,
                         const __nv_bfloat16* __restrict__ Kh,
                         const __nv_bfloat16* __restrict__ Kl,
                         const __nv_bfloat16* __restrict__ Vh,
                         const __nv_bfloat16* __restrict__ Vl,
                         const int* __restrict__ mask,
                         __nv_bfloat16* __restrict__ Ohi,
                         __nv_bfloat16* __restrict__ Olo)
{
    extern __shared__ char sm[];
    const uint32_t sb = smem_u32(sm);
    const uint32_t oQh = 0, oQl = 16384, oStage = 32768;
    const int tid  = threadIdx.x;
    const int lane = tid & 31;
    const int w    = tid >> 5;
    const int qt   = blockIdx.x;
    const int h    = blockIdx.y;
    const int b    = blockIdx.z;
    const int colh = h * HEAD_DIM;
    const size_t base = (size_t)b * SEQ * EMBED;
    const float CEXP = 1.4426950408889634f / 32.0f;

    // cp.async K/V/mask tile kt into stage kt&1
    auto issueKV = [&](int kt) {
        const uint32_t ksb = sb + oStage + (uint32_t)(kt & 1) * ATT_STAGE;
#pragma unroll
        for (int it = 0; it < 4; it++) {
            int idx = tid + it * 256;
            int r = idx >> 3, u = idx & 7;
            size_t g = base + (size_t)(kt * 128 + r) * EMBED + colh + u * 8;
            uint32_t so = (uint32_t)(r * 128 + ((u ^ (r & 7)) << 4));
            CP16(ksb             + so, Kh + g);
            CP16(ksb + 16384u    + so, Kl + g);
            CP16(ksb + 2*16384u  + so, Vh + g);
            CP16(ksb + 3*16384u  + so, Vl + g);
        }
        if (tid < 32)
            CP16(ksb + 4 * 16384u + (uint32_t)tid * 16u,
                 mask + b * SEQ + kt * 128 + tid * 4);
    };

    issueKV(0); CP_COMMIT();

    // Load Q tile (both planes) while stage-0 streams
#pragma unroll
    for (int it = 0; it < 4; it++) {
        int idx = tid + it * 256;
        int r = idx >> 3, u = idx & 7;
        size_t g = base + (size_t)(qt * 128 + r) * EMBED + colh + u * 8;
        uint32_t so = (uint32_t)(r * 128 + ((u ^ (r & 7)) << 4));
        *(uint4*)(sm + oQh + so) = *(const uint4*)(Qh + g);
        *(uint4*)(sm + oQl + so) = *(const uint4*)(Ql + g);
    }

    const int q0 = w * 16;
    float o[8][4];
#pragma unroll
    for (int j = 0; j < 8; j++)
#pragma unroll
        for (int q = 0; q < 4; q++) o[j][q] = 0.0f;
    const float NEG_INF = __int_as_float(0xff800000);
    float mr0 = NEG_INF, mr1 = NEG_INF, lr0 = 0.0f, lr1 = 0.0f;

    const uint32_t rowA = (uint32_t)(q0 + (lane & 15));
    const uint32_t uA   = (uint32_t)(lane >> 4);
    const uint32_t rowB = (uint32_t)((lane & 7) + ((lane >> 4) << 3));
    const uint32_t uB   = (uint32_t)((lane >> 3) & 1);
    const uint32_t rowV = (uint32_t)((lane & 7) + (((lane >> 3) & 1) << 3));
    const uint32_t uV   = (uint32_t)(lane >> 4);

    for (int kt = 0; kt < 16; kt++) {
        if (kt + 1 < 16) { issueKV(kt + 1); CP_COMMIT(); CP_WAIT(1); }
        else             { CP_WAIT(0); }
        __syncthreads();

        const uint32_t stg = sb + oStage + (uint32_t)(kt & 1) * ATT_STAGE;
        const uint32_t oKh = stg, oKl = stg + 16384, oVh = stg + 2 * 16384,
                       oVl = stg + 3 * 16384;
        const int* msk = (const int*)(sm + (oStage + (uint32_t)(kt & 1) * ATT_STAGE
                                            + 4 * 16384));

        // ---- S = Q K^T ----
        float s[16][4];
#pragma unroll
        for (int j = 0; j < 16; j++)
#pragma unroll
            for (int q = 0; q < 4; q++) s[j][q] = 0.0f;

#pragma unroll
        for (int ks = 0; ks < 4; ks++) {
            uint32_t ah[4], al[4];
            const uint32_t ua = uA + ks * 2;
            const uint32_t aoff = rowA * 128 + ((ua ^ (rowA & 7)) << 4);
            LDSM4(ah, sb + oQh + aoff);
            LDSM4(al, sb + oQl + aoff);
#pragma unroll
            for (int np = 0; np < 8; np++) {
                const uint32_t rb = rowB + np * 16;
                const uint32_t ub = uB + ks * 2;
                const uint32_t boff = rb * 128 + ((ub ^ (rb & 7)) << 4);
                uint32_t kh4[4], kl4[4];
                LDSM4(kh4, oKh + boff);
                LDSM4(kl4, oKl + boff);
                MMA16816(s[2 * np],     ah, kh4);
                MMA16816(s[2 * np],     al, kh4);
                MMA16816(s[2 * np],     ah, kl4);
                MMA16816(s[2 * np + 1], ah, kh4 + 2);
                MMA16816(s[2 * np + 1], al, kh4 + 2);
                MMA16816(s[2 * np + 1], ah, kl4 + 2);
            }
        }

        // ---- mask + online softmax ----
        const int cb2 = (lane & 3) * 2;
        float mx0 = NEG_INF, mx1 = NEG_INF;
#pragma unroll
        for (int j = 0; j < 16; j++) {
            const int col = j * 8 + cb2;
            const int m0v = msk[col], m1v = msk[col + 1];
            if (!m0v) { s[j][0] = -1e20f; s[j][2] = -1e20f; }
            if (!m1v) { s[j][1] = -1e20f; s[j][3] = -1e20f; }
            mx0 = fmaxf(mx0, fmaxf(s[j][0], s[j][1]));
            mx1 = fmaxf(mx1, fmaxf(s[j][2], s[j][3]));
        }
        mx0 = fmaxf(mx0, __shfl_xor_sync(0xffffffffu, mx0, 1));
        mx0 = fmaxf(mx0, __shfl_xor_sync(0xffffffffu, mx0, 2));
        mx1 = fmaxf(mx1, __shfl_xor_sync(0xffffffffu, mx1, 1));
        mx1 = fmaxf(mx1, __shfl_xor_sync(0xffffffffu, mx1, 2));

        const float mn0 = fmaxf(mr0, mx0);
        const float mn1 = fmaxf(mr1, mx1);
        const float c0 = fast_exp2((mr0 - mn0) * CEXP);
        const float c1 = fast_exp2((mr1 - mn1) * CEXP);
        mr0 = mn0; mr1 = mn1;

        float sum0 = 0.0f, sum1 = 0.0f;
#pragma unroll
        for (int j = 0; j < 16; j++) {
            s[j][0] = fast_exp2((s[j][0] - mn0) * CEXP);
            s[j][1] = fast_exp2((s[j][1] - mn0) * CEXP);
            s[j][2] = fast_exp2((s[j][2] - mn1) * CEXP);
            s[j][3] = fast_exp2((s[j][3] - mn1) * CEXP);
            sum0 += s[j][0] + s[j][1];
            sum1 += s[j][2] + s[j][3];
        }
        sum0 += __shfl_xor_sync(0xffffffffu, sum0, 1);
        sum0 += __shfl_xor_sync(0xffffffffu, sum0, 2);
        sum1 += __shfl_xor_sync(0xffffffffu, sum1, 1);
        sum1 += __shfl_xor_sync(0xffffffffu, sum1, 2);
        lr0 = lr0 * c0 + sum0;
        lr1 = lr1 * c1 + sum1;
#pragma unroll
        for (int jd = 0; jd < 8; jd++) {
            o[jd][0] *= c0; o[jd][1] *= c0;
            o[jd][2] *= c1; o[jd][3] *= c1;
        }

        // ---- S frags -> P A-frags (hi/lo) in registers ----
        uint32_t ph[8][4], pl[8][4];
#pragma unroll
        for (int kk = 0; kk < 8; kk++) {
            ph[kk][0] = split2(s[2 * kk][0],     s[2 * kk][1],     pl[kk][0]);
            ph[kk][1] = split2(s[2 * kk][2],     s[2 * kk][3],     pl[kk][1]);
            ph[kk][2] = split2(s[2 * kk + 1][0], s[2 * kk + 1][1], pl[kk][2]);
            ph[kk][3] = split2(s[2 * kk + 1][2], s[2 * kk + 1][3], pl[kk][3]);
        }

        // ---- O += P V ----
#pragma unroll
        for (int kk = 0; kk < 8; kk++) {
            const uint32_t k0 = kk * 16;
#pragma unroll
            for (int jdp = 0; jdp < 4; jdp++) {
                const uint32_t rv = k0 + rowV;
                const uint32_t uv = jdp * 2 + uV;
                const uint32_t voff = rv * 128 + ((uv ^ (rv & 7)) << 4);
                uint32_t bh4[4], bl4[4];
                LDSM4T(bh4, oVh + voff);
                LDSM4T(bl4, oVl + voff);
                MMA16816(o[2 * jdp],     ph[kk], bh4);
                MMA16816(o[2 * jdp],     pl[kk], bh4);
                MMA16816(o[2 * jdp],     ph[kk], bl4);
                MMA16816(o[2 * jdp + 1], ph[kk], bh4 + 2);
                MMA16816(o[2 * jdp + 1], pl[kk], bh4 + 2);
                MMA16816(o[2 * jdp + 1], ph[kk], bl4 + 2);
            }
        }
        __syncthreads();   // stage (kt+1)&1 safe to overwrite next iter
    }

    // ---- epilogue ----
    const float inv0 = 1.0f / lr0;
    const float inv1 = 1.0f / lr1;
    const int r0g = qt * 128 + q0 + (lane >> 2);
    const int cbe = (lane & 3) * 2;
#pragma unroll
    for (int jd = 0; jd < 8; jd++) {
        const int cn = colh + jd * 8 + cbe;
        uint32_t l0v, l1v;
        uint32_t h0v = split2(o[jd][0] * inv0, o[jd][1] * inv0, l0v);
        uint32_t h1v = split2(o[jd][2] * inv1, o[jd][3] * inv1, l1v);
        size_t i0 = base + (size_t)r0g * EMBED + cn;
        size_t i1 = base + (size_t)(r0g + 8) * EMBED + cn;
        *(uint32_t*)(Ohi + i0) = h0v;
        *(uint32_t*)(Olo + i0) = l0v;
        *(uint32_t*)(Ohi + i1) = h1v;
        *(uint32_t*)(Olo + i1) = l1v;
    }
}

// ---------------------------------------------------------------------------
// Launch
// ---------------------------------------------------------------------------
extern "C" void kernel_launch(void* const* d_in, const int* in_sizes, int n_in,
                              void* d_out, int out_size)
{
    const float* query = (const float*)d_in[0];
    const float* key   = (const float*)d_in[1];
    const float* value = (const float*)d_in[2];
    const int*   mask  = (const int*)  d_in[3];
    const float* Wq    = (const float*)d_in[4];
    const float* bq    = (const float*)d_in[5];
    const float* Wk    = (const float*)d_in[6];
    const float* bk    = (const float*)d_in[7];
    const float* Wv    = (const float*)d_in[8];
    const float* bv    = (const float*)d_in[9];
    const float* Wo    = (const float*)d_in[10];
    const float* bo    = (const float*)d_in[11];
    float* out = (float*)d_out;

    __nv_bfloat16 *ih, *il, *wh, *wl, *aoh, *aol;
    __nv_bfloat16 *qh, *ql, *kh, *kl, *vh, *vl;
    cudaGetSymbolAddress((void**)&ih,  g_in_hi);
    cudaGetSymbolAddress((void**)&il,  g_in_lo);
    cudaGetSymbolAddress((void**)&wh,  g_w_hi);
    cudaGetSymbolAddress((void**)&wl,  g_w_lo);
    cudaGetSymbolAddress((void**)&aoh, g_ao_hi);
    cudaGetSymbolAddress((void**)&aol, g_ao_lo);
    cudaGetSymbolAddress((void**)&qh,  g_qh);
    cudaGetSymbolAddress((void**)&ql,  g_ql);
    cudaGetSymbolAddress((void**)&kh,  g_kh);
    cudaGetSymbolAddress((void**)&kl,  g_kl);
    cudaGetSymbolAddress((void**)&vh,  g_vh);
    cudaGetSymbolAddress((void**)&vl,  g_vl);

    cudaFuncSetAttribute(gemm_bf16x3_kernel,
                         cudaFuncAttributeMaxDynamicSharedMemorySize, GEMM_SMEM);
    cudaFuncSetAttribute(attention_tc_kernel,
                         cudaFuncAttributeMaxDynamicSharedMemorySize, ATT_SMEM);

    // One fused split pass: 3 inputs + 4 weights -> bf16 hi/lo planes
    const int NI = TOKENS * EMBED / 4;
    const int NW = EMBED * EMBED / 4;
    cvt_split_all_kernel<<<(3 * NI + 4 * NW) / 256, 256>>>(
        (const float4*)query, (const float4*)key, (const float4*)value,
        (const float4*)Wq, (const float4*)Wk, (const float4*)Wv, (const float4*)Wo,
        (uint2*)ih, (uint2*)il, (uint2*)wh, (uint2*)wl);

    // QKV projections -> bf16 hi/lo planes directly
    gemm_bf16x3_kernel<<<dim3(EMBED / 128, TOKENS / 128, 3), 256, GEMM_SMEM>>>(
        ih, il, TOKENS * EMBED, wh, wl, EMBED * EMBED,
        bq, bk, bv, nullptr, qh, kh, vh, ql, kl, vl);

    // Tensor-core flash attention
    attention_tc_kernel<<<dim3(SEQ / 128, HEADS, BATCH), 256, ATT_SMEM>>>(
        qh, ql, kh, kl, vh, vl, mask, aoh, aol);

    // Output projection -> fp32
    gemm_bf16x3_kernel<<<dim3(EMBED / 128, TOKENS / 128, 1), 256, GEMM_SMEM>>>(
        aoh, aol, 0, wh + (size_t)3 * EMBED * EMBED, wl + (size_t)3 * EMBED * EMBED, 0,
        bo, bo, bo, out,
        nullptr, nullptr, nullptr, nullptr, nullptr, nullptr);
}

// round 6
// speedup vs baseline: 2.9836x; 1.0269x over previous
#include <cuda_runtime.h>
#include <cuda_bf16.h>
#include <cstdint>
#include <math.h>

#define EMBED    1024
#define HEADS    16
#define HEAD_DIM 64
#define BATCH    2
#define SEQ      2048
#define TOKENS   (BATCH * SEQ)

// ---------------------------------------------------------------------------
// Scratch (device globals)
// ---------------------------------------------------------------------------
__device__ __nv_bfloat16 g_in_hi[3 * TOKENS * EMBED];
__device__ __nv_bfloat16 g_in_lo[3 * TOKENS * EMBED];
__device__ __nv_bfloat16 g_w_hi [4 * EMBED * EMBED];
__device__ __nv_bfloat16 g_w_lo [4 * EMBED * EMBED];
__device__ __nv_bfloat16 g_qh[TOKENS * EMBED], g_ql[TOKENS * EMBED];
__device__ __nv_bfloat16 g_kh[TOKENS * EMBED], g_kl[TOKENS * EMBED];
__device__ __nv_bfloat16 g_vh[TOKENS * EMBED], g_vl[TOKENS * EMBED];
__device__ __nv_bfloat16 g_ao_hi[TOKENS * EMBED];
__device__ __nv_bfloat16 g_ao_lo[TOKENS * EMBED];

__device__ __forceinline__ uint32_t smem_u32(const void* p) {
    uint32_t a;
    asm("{ .reg .u64 t; cvta.to.shared.u64 t, %1; cvt.u32.u64 %0, t; }"
        : "=r"(a) : "l"(p));
    return a;
}
__device__ __forceinline__ float fast_exp2(float x) {
    float y;
    asm("ex2.approx.f32 %0, %1;" : "=f"(y) : "f"(x));
    return y;
}
__device__ __forceinline__ uint32_t split2(float a, float b, uint32_t& lo) {
    __nv_bfloat162 h = __floats2bfloat162_rn(a, b);
    __nv_bfloat162 l = __floats2bfloat162_rn(
        a - __bfloat162float(__low2bfloat16(h)),
        b - __bfloat162float(__high2bfloat16(h)));
    lo = *reinterpret_cast<uint32_t*>(&l);
    return *reinterpret_cast<uint32_t*>(&h);
}

#define LDSM4(r, a) \
    asm volatile("ldmatrix.sync.aligned.m8n8.x4.shared.b16 {%0,%1,%2,%3}, [%4];" \
                 : "=r"((r)[0]), "=r"((r)[1]), "=r"((r)[2]), "=r"((r)[3]) : "r"(a))
#define LDSM4T(r, a) \
    asm volatile("ldmatrix.sync.aligned.m8n8.x4.trans.shared.b16 {%0,%1,%2,%3}, [%4];" \
                 : "=r"((r)[0]), "=r"((r)[1]), "=r"((r)[2]), "=r"((r)[3]) : "r"(a))
#define MMA16816(d, a, b) \
    asm volatile("mma.sync.aligned.m16n8k16.row.col.f32.bf16.bf16.f32 " \
                 "{%0,%1,%2,%3}, {%4,%5,%6,%7}, {%8,%9}, {%0,%1,%2,%3};" \
                 : "+f"((d)[0]), "+f"((d)[1]), "+f"((d)[2]), "+f"((d)[3]) \
                 : "r"((a)[0]), "r"((a)[1]), "r"((a)[2]), "r"((a)[3]), \
                   "r"((b)[0]), "r"((b)[1]))
#define CP16(dst, src) \
    asm volatile("cp.async.ca.shared.global [%0], [%1], 16;" \
                 :: "r"(dst), "l"(src) : "memory")
#define CP_COMMIT() asm volatile("cp.async.commit_group;" ::: "memory")
#define CP_WAIT(n)  asm volatile("cp.async.wait_group %0;" :: "n"(n) : "memory")

// ---------------------------------------------------------------------------
// Fused fp32 -> bf16 hi/lo split (one launch for 3 inputs + 4 weights)
// ---------------------------------------------------------------------------
__global__ __launch_bounds__(256)
void cvt_split_all_kernel(const float4* __restrict__ q, const float4* __restrict__ k,
                          const float4* __restrict__ v,
                          const float4* __restrict__ wq, const float4* __restrict__ wk,
                          const float4* __restrict__ wv, const float4* __restrict__ wo,
                          uint2* __restrict__ ih, uint2* __restrict__ il,
                          uint2* __restrict__ wh, uint2* __restrict__ wl)
{
    const int NI = TOKENS * EMBED / 4;
    const int NW = EMBED * EMBED / 4;
    int i = blockIdx.x * 256 + threadIdx.x;

    const float4* src;
    uint2 *H, *L;
    if (i < 3 * NI) {
        int seg = i / NI;
        int off = i - seg * NI;
        src = (seg == 0 ? q : seg == 1 ? k : v) + off;
        H = ih + (size_t)seg * NI + off;
        L = il + (size_t)seg * NI + off;
    } else {
        int j = i - 3 * NI;
        int seg = j / NW;
        int off = j - seg * NW;
        src = (seg == 0 ? wq : seg == 1 ? wk : seg == 2 ? wv : wo) + off;
        H = wh + (size_t)seg * NW + off;
        L = wl + (size_t)seg * NW + off;
    }
    float4 val = *src;
    uint2 Hv, Lv;
    Hv.x = split2(val.x, val.y, Lv.x);
    Hv.y = split2(val.z, val.w, Lv.y);
    *H = Hv;
    *L = Lv;
}

// ---------------------------------------------------------------------------
// bf16x3 tensor-core GEMM: 128x128 CTA, BK=32, 8 warps, 3-stage cp.async.
// __launch_bounds__(256, 2): <=128 regs so 2 CTAs/SM are resident.
// ---------------------------------------------------------------------------
__device__ __forceinline__ uint32_t swz(int m, int c) {
    return (uint32_t)((m >> 1) * 128 + (((((m & 1) << 2) | c) ^ ((m >> 1) & 7)) << 4));
}

#define GEMM_SMEM (3 * 4 * 8192)   // 96KB; x2 CTAs = 192KB <= 228KB

__global__ __launch_bounds__(256, 2)
void gemm_bf16x3_kernel(const __nv_bfloat16* __restrict__ Ahi_b,
                        const __nv_bfloat16* __restrict__ Alo_b,
                        int strideAz,
                        const __nv_bfloat16* __restrict__ Whi_b,
                        const __nv_bfloat16* __restrict__ Wlo_b,
                        int strideWz,
                        const float* __restrict__ b0, const float* __restrict__ b1,
                        const float* __restrict__ b2,
                        float* __restrict__ Cf,
                        __nv_bfloat16* __restrict__ H0, __nv_bfloat16* __restrict__ H1,
                        __nv_bfloat16* __restrict__ H2,
                        __nv_bfloat16* __restrict__ L0, __nv_bfloat16* __restrict__ L1,
                        __nv_bfloat16* __restrict__ L2)
{
    extern __shared__ char sm[];
    const uint32_t sb = smem_u32(sm);
    const int tid  = threadIdx.x;
    const int wid  = tid >> 5;
    const int lane = tid & 31;

    const int z = blockIdx.z;
    const __nv_bfloat16* Ahi = Ahi_b + (size_t)z * strideAz;
    const __nv_bfloat16* Alo = Alo_b + (size_t)z * strideAz;
    const __nv_bfloat16* Whi = Whi_b + (size_t)z * strideWz;
    const __nv_bfloat16* Wlo = Wlo_b + (size_t)z * strideWz;
    const float* bias = (z == 0) ? b0 : (z == 1) ? b1 : b2;

    const int row0 = blockIdx.y * 128;
    const int col0 = blockIdx.x * 128;
    const int wm = (wid & 1) * 64;
    const int wn = (wid >> 1) * 32;

    const int lm = tid >> 1;
    const int lc = (tid & 1) * 2;
    const __nv_bfloat16* gAh = Ahi + (size_t)(row0 + lm) * EMBED + lc * 8;
    const __nv_bfloat16* gAl = Alo + (size_t)(row0 + lm) * EMBED + lc * 8;
    const __nv_bfloat16* gWh = Whi + (size_t)(col0 + lm) * EMBED + lc * 8;
    const __nv_bfloat16* gWl = Wlo + (size_t)(col0 + lm) * EMBED + lc * 8;
    const uint32_t s0 = swz(lm, lc);
    const uint32_t s1 = swz(lm, lc + 1);

    float acc[4][4][4];
#pragma unroll
    for (int i = 0; i < 4; i++)
#pragma unroll
        for (int j = 0; j < 4; j++)
#pragma unroll
            for (int q = 0; q < 4; q++) acc[i][j][q] = 0.0f;

    auto issue = [&](int ch) {
        const uint32_t st = sb + (uint32_t)(ch % 3) * 32768u;
        const int ko = ch * 32;
        CP16(st             + s0, gAh + ko);
        CP16(st             + s1, gAh + ko + 8);
        CP16(st +     8192u + s0, gAl + ko);
        CP16(st +     8192u + s1, gAl + ko + 8);
        CP16(st + 2 * 8192u + s0, gWh + ko);
        CP16(st + 2 * 8192u + s1, gWh + ko + 8);
        CP16(st + 3 * 8192u + s0, gWl + ko);
        CP16(st + 3 * 8192u + s1, gWl + ko + 8);
    };

    issue(0); CP_COMMIT();
    issue(1); CP_COMMIT();

    const int mA  = wm + (lane & 7) + ((lane >> 3) & 1) * 8;
    const int cA  = (lane >> 4);
    const int nB4 = wn + (lane & 7) + ((lane >> 4) << 3);
    const int cB4 = ((lane >> 3) & 1);

    const int NCHUNK = EMBED / 32;
    for (int ch = 0; ch < NCHUNK; ch++) {
        if (ch + 1 < NCHUNK) { CP_WAIT(1); } else { CP_WAIT(0); }
        __syncthreads();
        if (ch + 2 < NCHUNK) { issue(ch + 2); CP_COMMIT(); }

        const uint32_t stb = sb + (uint32_t)(ch % 3) * 32768u;
#pragma unroll
        for (int ks = 0; ks < 2; ks++) {
            uint32_t ah[4][4], al[4][4], bh[4][2], bl[4][2];
            const int ca = ks * 2 + cA;
            const int cb = ks * 2 + cB4;
#pragma unroll
            for (int i = 0; i < 4; i++) {
                LDSM4(ah[i], stb        + swz(mA + i * 16, ca));
                LDSM4(al[i], stb + 8192 + swz(mA + i * 16, ca));
            }
#pragma unroll
            for (int jj = 0; jj < 2; jj++) {
                uint32_t t[4];
                LDSM4(t, stb + 2 * 8192 + swz(nB4 + jj * 16, cb));
                bh[2 * jj][0] = t[0]; bh[2 * jj][1] = t[1];
                bh[2 * jj + 1][0] = t[2]; bh[2 * jj + 1][1] = t[3];
                LDSM4(t, stb + 3 * 8192 + swz(nB4 + jj * 16, cb));
                bl[2 * jj][0] = t[0]; bl[2 * jj][1] = t[1];
                bl[2 * jj + 1][0] = t[2]; bl[2 * jj + 1][1] = t[3];
            }
#pragma unroll
            for (int i = 0; i < 4; i++)
#pragma unroll
                for (int j = 0; j < 4; j++) {
                    MMA16816(acc[i][j], ah[i], bh[j]);
                    MMA16816(acc[i][j], al[i], bh[j]);
                    MMA16816(acc[i][j], ah[i], bl[j]);
                }
        }
    }

    const int mrow = row0 + wm + (lane >> 2);
    const int ncol = col0 + wn + (lane & 3) * 2;
    if (H0) {
        __nv_bfloat16* Hi = (z == 0) ? H0 : (z == 1) ? H1 : H2;
        __nv_bfloat16* Lo = (z == 0) ? L0 : (z == 1) ? L1 : L2;
#pragma unroll
        for (int i = 0; i < 4; i++)
#pragma unroll
            for (int j = 0; j < 4; j++) {
                const int r  = mrow + i * 16;
                const int cn = ncol + j * 8;
                const float bx = bias[cn], by = bias[cn + 1];
                uint32_t l0v, l1v;
                uint32_t h0v = split2(acc[i][j][0] + bx, acc[i][j][1] + by, l0v);
                uint32_t h1v = split2(acc[i][j][2] + bx, acc[i][j][3] + by, l1v);
                *(uint32_t*)(Hi + (size_t)r       * EMBED + cn) = h0v;
                *(uint32_t*)(Lo + (size_t)r       * EMBED + cn) = l0v;
                *(uint32_t*)(Hi + (size_t)(r + 8) * EMBED + cn) = h1v;
                *(uint32_t*)(Lo + (size_t)(r + 8) * EMBED + cn) = l1v;
            }
    } else {
#pragma unroll
        for (int i = 0; i < 4; i++)
#pragma unroll
            for (int j = 0; j < 4; j++) {
                const int r  = mrow + i * 16;
                const int cn = ncol + j * 8;
                const float bx = bias[cn], by = bias[cn + 1];
                float2 v0 = make_float2(acc[i][j][0] + bx, acc[i][j][1] + by);
                float2 v1 = make_float2(acc[i][j][2] + bx, acc[i][j][3] + by);
                *(float2*)(Cf + (size_t)r       * EMBED + cn) = v0;
                *(float2*)(Cf + (size_t)(r + 8) * EMBED + cn) = v1;
            }
    }
}

// ---------------------------------------------------------------------------
// Tensor-core flash attention (bf16x3). K-tile = 64 (32 iters), 2-stage
// cp.async, transient P conversion -> ~110 regs, 97KB smem -> 2 CTAs/SM.
// CTA = 128 q x (b,h). 8 warps, warp tile 16q x 64k.
// ---------------------------------------------------------------------------
#define KT 64
#define ATT_STAGE (4 * 8192 + 256)              // Kh Kl Vh Vl + mask
#define ATT_SMEM  (2 * 16384 + 2 * ATT_STAGE)   // 98816 B; x2 CTAs <= 228KB

__global__ __launch_bounds__(256, 2)
void attention_tc_kernel(const __nv_bfloat16* __restrict__ Qh,
                         const __nv_bfloat16* __restrict__ Ql,
                         const __nv_bfloat16* __restrict__ Kh,
                         const __nv_bfloat16* __restrict__ Kl,
                         const __nv_bfloat16* __restrict__ Vh,
                         const __nv_bfloat16* __restrict__ Vl,
                         const int* __restrict__ mask,
                         __nv_bfloat16* __restrict__ Ohi,
                         __nv_bfloat16* __restrict__ Olo)
{
    extern __shared__ char sm[];
    const uint32_t sb = smem_u32(sm);
    const uint32_t oQh = 0, oQl = 16384, oStage = 32768;
    const int tid  = threadIdx.x;
    const int lane = tid & 31;
    const int w    = tid >> 5;
    const int qt   = blockIdx.x;
    const int h    = blockIdx.y;
    const int b    = blockIdx.z;
    const int colh = h * HEAD_DIM;
    const size_t base = (size_t)b * SEQ * EMBED;
    const float CEXP = 1.4426950408889634f / 32.0f;

    // cp.async K/V/mask tile kt (64 rows x 64 d) into stage kt&1
    auto issueKV = [&](int kt) {
        const uint32_t ksb = sb + oStage + (uint32_t)(kt & 1) * ATT_STAGE;
#pragma unroll
        for (int it = 0; it < 2; it++) {
            int idx = tid + it * 256;           // 0..511
            int r = idx >> 3, u = idx & 7;
            size_t g = base + (size_t)(kt * KT + r) * EMBED + colh + u * 8;
            uint32_t so = (uint32_t)(r * 128 + ((u ^ (r & 7)) << 4));
            CP16(ksb            + so, Kh + g);
            CP16(ksb +     8192u + so, Kl + g);
            CP16(ksb + 2 * 8192u + so, Vh + g);
            CP16(ksb + 3 * 8192u + so, Vl + g);
        }
        if (tid < 16)
            CP16(ksb + 4 * 8192u + (uint32_t)tid * 16u,
                 mask + b * SEQ + kt * KT + tid * 4);
    };

    issueKV(0); CP_COMMIT();

    // Load Q tile (both planes) while stage-0 streams
#pragma unroll
    for (int it = 0; it < 4; it++) {
        int idx = tid + it * 256;
        int r = idx >> 3, u = idx & 7;
        size_t g = base + (size_t)(qt * 128 + r) * EMBED + colh + u * 8;
        uint32_t so = (uint32_t)(r * 128 + ((u ^ (r & 7)) << 4));
        *(uint4*)(sm + oQh + so) = *(const uint4*)(Qh + g);
        *(uint4*)(sm + oQl + so) = *(const uint4*)(Ql + g);
    }

    const int q0 = w * 16;
    float o[8][4];
#pragma unroll
    for (int j = 0; j < 8; j++)
#pragma unroll
        for (int q = 0; q < 4; q++) o[j][q] = 0.0f;
    const float NEG_INF = __int_as_float(0xff800000);
    float mr0 = NEG_INF, mr1 = NEG_INF, lr0 = 0.0f, lr1 = 0.0f;

    const uint32_t rowA = (uint32_t)(q0 + (lane & 15));
    const uint32_t uA   = (uint32_t)(lane >> 4);
    const uint32_t rowB = (uint32_t)((lane & 7) + ((lane >> 4) << 3));
    const uint32_t uB   = (uint32_t)((lane >> 3) & 1);
    const uint32_t rowV = (uint32_t)((lane & 7) + (((lane >> 3) & 1) << 3));
    const uint32_t uV   = (uint32_t)(lane >> 4);

    const int NITER = SEQ / KT;   // 32
    for (int kt = 0; kt < NITER; kt++) {
        if (kt + 1 < NITER) { issueKV(kt + 1); CP_COMMIT(); CP_WAIT(1); }
        else                { CP_WAIT(0); }
        __syncthreads();

        const uint32_t stg = sb + oStage + (uint32_t)(kt & 1) * ATT_STAGE;
        const uint32_t oKh = stg, oKl = stg + 8192, oVh = stg + 2 * 8192,
                       oVl = stg + 3 * 8192;
        const int* msk = (const int*)(sm + (oStage + (uint32_t)(kt & 1) * ATT_STAGE
                                            + 4 * 8192));

        // ---- S = Q K^T : 8 n8-tiles per warp (64 k) ----
        float s[8][4];
#pragma unroll
        for (int j = 0; j < 8; j++)
#pragma unroll
            for (int q = 0; q < 4; q++) s[j][q] = 0.0f;

#pragma unroll
        for (int ks = 0; ks < 4; ks++) {
            uint32_t ah[4], al[4];
            const uint32_t ua = uA + ks * 2;
            const uint32_t aoff = rowA * 128 + ((ua ^ (rowA & 7)) << 4);
            LDSM4(ah, sb + oQh + aoff);
            LDSM4(al, sb + oQl + aoff);
#pragma unroll
            for (int np = 0; np < 4; np++) {
                const uint32_t rb = rowB + np * 16;
                const uint32_t ub = uB + ks * 2;
                const uint32_t boff = rb * 128 + ((ub ^ (rb & 7)) << 4);
                uint32_t kh4[4], kl4[4];
                LDSM4(kh4, oKh + boff);
                LDSM4(kl4, oKl + boff);
                MMA16816(s[2 * np],     ah, kh4);
                MMA16816(s[2 * np],     al, kh4);
                MMA16816(s[2 * np],     ah, kl4);
                MMA16816(s[2 * np + 1], ah, kh4 + 2);
                MMA16816(s[2 * np + 1], al, kh4 + 2);
                MMA16816(s[2 * np + 1], ah, kl4 + 2);
            }
        }

        // ---- mask + online softmax ----
        const int cb2 = (lane & 3) * 2;
        float mx0 = NEG_INF, mx1 = NEG_INF;
#pragma unroll
        for (int j = 0; j < 8; j++) {
            const int col = j * 8 + cb2;
            const int m0v = msk[col], m1v = msk[col + 1];
            if (!m0v) { s[j][0] = -1e20f; s[j][2] = -1e20f; }
            if (!m1v) { s[j][1] = -1e20f; s[j][3] = -1e20f; }
            mx0 = fmaxf(mx0, fmaxf(s[j][0], s[j][1]));
            mx1 = fmaxf(mx1, fmaxf(s[j][2], s[j][3]));
        }
        mx0 = fmaxf(mx0, __shfl_xor_sync(0xffffffffu, mx0, 1));
        mx0 = fmaxf(mx0, __shfl_xor_sync(0xffffffffu, mx0, 2));
        mx1 = fmaxf(mx1, __shfl_xor_sync(0xffffffffu, mx1, 1));
        mx1 = fmaxf(mx1, __shfl_xor_sync(0xffffffffu, mx1, 2));

        const float mn0 = fmaxf(mr0, mx0);
        const float mn1 = fmaxf(mr1, mx1);
        const float c0 = fast_exp2((mr0 - mn0) * CEXP);
        const float c1 = fast_exp2((mr1 - mn1) * CEXP);
        mr0 = mn0; mr1 = mn1;

        float sum0 = 0.0f, sum1 = 0.0f;
#pragma unroll
        for (int j = 0; j < 8; j++) {
            s[j][0] = fast_exp2((s[j][0] - mn0) * CEXP);
            s[j][1] = fast_exp2((s[j][1] - mn0) * CEXP);
            s[j][2] = fast_exp2((s[j][2] - mn1) * CEXP);
            s[j][3] = fast_exp2((s[j][3] - mn1) * CEXP);
            sum0 += s[j][0] + s[j][1];
            sum1 += s[j][2] + s[j][3];
        }
        sum0 += __shfl_xor_sync(0xffffffffu, sum0, 1);
        sum0 += __shfl_xor_sync(0xffffffffu, sum0, 2);
        sum1 += __shfl_xor_sync(0xffffffffu, sum1, 1);
        sum1 += __shfl_xor_sync(0xffffffffu, sum1, 2);
        lr0 = lr0 * c0 + sum0;
        lr1 = lr1 * c1 + sum1;
#pragma unroll
        for (int jd = 0; jd < 8; jd++) {
            o[jd][0] *= c0; o[jd][1] *= c0;
            o[jd][2] *= c1; o[jd][3] *= c1;
        }

        // ---- O += P V : convert P per 16-k slab (transient), then MMA ----
#pragma unroll
        for (int kk = 0; kk < 4; kk++) {
            uint32_t ph[4], pl[4];
            ph[0] = split2(s[2 * kk][0],     s[2 * kk][1],     pl[0]);
            ph[1] = split2(s[2 * kk][2],     s[2 * kk][3],     pl[1]);
            ph[2] = split2(s[2 * kk + 1][0], s[2 * kk + 1][1], pl[2]);
            ph[3] = split2(s[2 * kk + 1][2], s[2 * kk + 1][3], pl[3]);
            const uint32_t k0 = kk * 16;
#pragma unroll
            for (int jdp = 0; jdp < 4; jdp++) {
                const uint32_t rv = k0 + rowV;
                const uint32_t uv = jdp * 2 + uV;
                const uint32_t voff = rv * 128 + ((uv ^ (rv & 7)) << 4);
                uint32_t bh4[4], bl4[4];
                LDSM4T(bh4, oVh + voff);
                LDSM4T(bl4, oVl + voff);
                MMA16816(o[2 * jdp],     ph, bh4);
                MMA16816(o[2 * jdp],     pl, bh4);
                MMA16816(o[2 * jdp],     ph, bl4);
                MMA16816(o[2 * jdp + 1], ph, bh4 + 2);
                MMA16816(o[2 * jdp + 1], pl, bh4 + 2);
                MMA16816(o[2 * jdp + 1], ph, bl4 + 2);
            }
        }
        __syncthreads();
    }

    // ---- epilogue ----
    const float inv0 = 1.0f / lr0;
    const float inv1 = 1.0f / lr1;
    const int r0g = qt * 128 + q0 + (lane >> 2);
    const int cbe = (lane & 3) * 2;
#pragma unroll
    for (int jd = 0; jd < 8; jd++) {
        const int cn = colh + jd * 8 + cbe;
        uint32_t l0v, l1v;
        uint32_t h0v = split2(o[jd][0] * inv0, o[jd][1] * inv0, l0v);
        uint32_t h1v = split2(o[jd][2] * inv1, o[jd][3] * inv1, l1v);
        size_t i0 = base + (size_t)r0g * EMBED + cn;
        size_t i1 = base + (size_t)(r0g + 8) * EMBED + cn;
        *(uint32_t*)(Ohi + i0) = h0v;
        *(uint32_t*)(Olo + i0) = l0v;
        *(uint32_t*)(Ohi + i1) = h1v;
        *(uint32_t*)(Olo + i1) = l1v;
    }
}

// ---------------------------------------------------------------------------
// Launch
// ---------------------------------------------------------------------------
extern "C" void kernel_launch(void* const* d_in, const int* in_sizes, int n_in,
                              void* d_out, int out_size)
{
    const float* query = (const float*)d_in[0];
    const float* key   = (const float*)d_in[1];
    const float* value = (const float*)d_in[2];
    const int*   mask  = (const int*)  d_in[3];
    const float* Wq    = (const float*)d_in[4];
    const float* bq    = (const float*)d_in[5];
    const float* Wk    = (const float*)d_in[6];
    const float* bk    = (const float*)d_in[7];
    const float* Wv    = (const float*)d_in[8];
    const float* bv    = (const float*)d_in[9];
    const float* Wo    = (const float*)d_in[10];
    const float* bo    = (const float*)d_in[11];
    float* out = (float*)d_out;

    __nv_bfloat16 *ih, *il, *wh, *wl, *aoh, *aol;
    __nv_bfloat16 *qh, *ql, *kh, *kl, *vh, *vl;
    cudaGetSymbolAddress((void**)&ih,  g_in_hi);
    cudaGetSymbolAddress((void**)&il,  g_in_lo);
    cudaGetSymbolAddress((void**)&wh,  g_w_hi);
    cudaGetSymbolAddress((void**)&wl,  g_w_lo);
    cudaGetSymbolAddress((void**)&aoh, g_ao_hi);
    cudaGetSymbolAddress((void**)&aol, g_ao_lo);
    cudaGetSymbolAddress((void**)&qh,  g_qh);
    cudaGetSymbolAddress((void**)&ql,  g_ql);
    cudaGetSymbolAddress((void**)&kh,  g_kh);
    cudaGetSymbolAddress((void**)&kl,  g_kl);
    cudaGetSymbolAddress((void**)&vh,  g_vh);
    cudaGetSymbolAddress((void**)&vl,  g_vl);

    cudaFuncSetAttribute(gemm_bf16x3_kernel,
                         cudaFuncAttributeMaxDynamicSharedMemorySize, GEMM_SMEM);
    cudaFuncSetAttribute(attention_tc_kernel,
                         cudaFuncAttributeMaxDynamicSharedMemorySize, ATT_SMEM);

    // One fused split pass
    const int NI = TOKENS * EMBED / 4;
    const int NW = EMBED * EMBED / 4;
    cvt_split_all_kernel<<<(3 * NI + 4 * NW) / 256, 256>>>(
        (const float4*)query, (const float4*)key, (const float4*)value,
        (const float4*)Wq, (const float4*)Wk, (const float4*)Wv, (const float4*)Wo,
        (uint2*)ih, (uint2*)il, (uint2*)wh, (uint2*)wl);

    // QKV projections -> bf16 hi/lo planes
    gemm_bf16x3_kernel<<<dim3(EMBED / 128, TOKENS / 128, 3), 256, GEMM_SMEM>>>(
        ih, il, TOKENS * EMBED, wh, wl, EMBED * EMBED,
        bq, bk, bv, nullptr, qh, kh, vh, ql, kl, vl);

    // Tensor-core flash attention
    attention_tc_kernel<<<dim3(SEQ / 128, HEADS, BATCH), 256, ATT_SMEM>>>(
        qh, ql, kh, kl, vh, vl, mask, aoh, aol);

    // Output projection -> fp32
    gemm_bf16x3_kernel<<<dim3(EMBED / 128, TOKENS / 128, 1), 256, GEMM_SMEM>>>(
        aoh, aol, 0, wh + (size_t)3 * EMBED * EMBED, wl + (size_t)3 * EMBED * EMBED, 0,
        bo, bo, bo, out,
        nullptr, nullptr, nullptr, nullptr, nullptr, nullptr);
}